// round 3
// baseline (speedup 1.0000x reference)
#include <cuda_runtime.h>
#include <cstdint>
#include <cstddef>

// Problem constants
#define BB   32
#define CC   256
#define HH   56
#define WW   56
#define HWSZ 3136          // 56*56
#define GG   4
#define KS   7
#define KK2  49            // 7*7
#define CRR  64            // C / 4
#define NTOT (BB * HWSZ)   // 100352 = 392 * 256

typedef unsigned long long ull;

// Scratch (device globals: allocation-free per harness rules)
__device__ float g_scratch[(size_t)BB * CC * HWSZ];   // gelu(dwconv(s)) : ~103 MB
__device__ float g_pooled[BB * CC];
__device__ float g_wk[(size_t)BB * CC * KK2];         // per-(b,c) 7x7 kernels

// ---------------------------------------------------------------------------
// helpers
// ---------------------------------------------------------------------------
__device__ __forceinline__ float gelu_f(float x) {
    return 0.5f * x * (1.0f + erff(x * 0.70710678118654752440f));
}
__device__ __forceinline__ ull pack2(float lo, float hi) {
    ull r; asm("mov.b64 %0, {%1, %2};" : "=l"(r) : "f"(lo), "f"(hi)); return r;
}
__device__ __forceinline__ void fma2(ull& d, ull a, ull b) {
    asm("fma.rn.f32x2 %0, %1, %2, %0;" : "+l"(d) : "l"(a), "l"(b));
}
__device__ __forceinline__ float2 unpack2(ull v) {
    float2 r; asm("mov.b64 {%0, %1}, %2;" : "=f"(r.x), "=f"(r.y) : "l"(v)); return r;
}

// ---------------------------------------------------------------------------
// Kernel 1: pooled[b,c] = mean over H,W of r
// ---------------------------------------------------------------------------
__global__ void pool_kernel(const float* __restrict__ r) {
    const int bc = blockIdx.x;
    const float4* p = reinterpret_cast<const float4*>(r + (size_t)bc * HWSZ);
    float s = 0.f;
    for (int i = threadIdx.x; i < HWSZ / 4; i += blockDim.x) {
        float4 v = p[i];
        s += v.x + v.y + v.z + v.w;
    }
    __shared__ float red[8];
    #pragma unroll
    for (int o = 16; o > 0; o >>= 1) s += __shfl_down_sync(0xFFFFFFFFu, s, o);
    if ((threadIdx.x & 31) == 0) red[threadIdx.x >> 5] = s;
    __syncthreads();
    if (threadIdx.x < 8) {
        s = red[threadIdx.x];
        #pragma unroll
        for (int o = 4; o > 0; o >>= 1) s += __shfl_down_sync(0xFFu, s, o);
        if (threadIdx.x == 0) g_pooled[bc] = s * (1.0f / (float)HWSZ);
    }
}

// ---------------------------------------------------------------------------
// Kernel 2: SE weight generation -> g_wk[b,c,49]
// ---------------------------------------------------------------------------
__global__ void wgen_kernel(const float* __restrict__ w1, const float* __restrict__ b1,
                            const float* __restrict__ w2, const float* __restrict__ b2,
                            const float* __restrict__ weight, const float* __restrict__ bscale) {
    const int b = blockIdx.x;
    const int t = threadIdx.x;
    __shared__ float ps[CC];
    __shared__ float hs[CRR];

    ps[t] = g_pooled[b * CC + t];
    __syncthreads();

    if (t < CRR) {
        float acc = b1[t];
        const float* wr = w1 + (size_t)t * CC;
        #pragma unroll 4
        for (int c = 0; c < CC; c++) acc = fmaf(ps[c], wr[c], acc);
        hs[t] = gelu_f(acc);
    }
    __syncthreads();

    float vals[GG][2];
    #pragma unroll
    for (int g = 0; g < GG; g++) {
        #pragma unroll
        for (int e = 0; e < 2; e++) {
            const int row = (g * CC + t) * 2 + e;
            float acc = b2[row];
            const float* wr = w2 + (size_t)row * CRR;
            #pragma unroll 4
            for (int k = 0; k < CRR; k++) acc = fmaf(hs[k], wr[k], acc);
            vals[g][e] = acc;
        }
    }

    float m = fmaxf(fmaxf(vals[0][0], vals[1][0]), fmaxf(vals[2][0], vals[3][0]));
    float alpha[GG];
    float ssum = 0.f;
    #pragma unroll
    for (int g = 0; g < GG; g++) { alpha[g] = expf(vals[g][0] - m); ssum += alpha[g]; }
    const float inv = 1.0f / ssum;
    float betasum = 0.f;
    #pragma unroll
    for (int g = 0; g < GG; g++) {
        alpha[g] *= inv;
        betasum += tanhf(vals[g][1] * expf(bscale[g * CC + t]) * 0.1f);
    }

    float* out = g_wk + ((size_t)b * CC + t) * KK2;
    #pragma unroll
    for (int k = 0; k < KK2; k++) {
        float acc = betasum;
        #pragma unroll
        for (int g = 0; g < GG; g++)
            acc = fmaf(alpha[g], weight[((size_t)g * CC + t) * KK2 + k], acc);
        out[k] = acc;
    }
}

// ---------------------------------------------------------------------------
// Kernel 3: dynamic depthwise 7x7 conv (pad 3) + exact GELU -> g_scratch
// 2 planes per 128-thread block. Per-thread tile: 7(y) x 8(x).
// Weights pre-packed (w,w) in smem, read via broadcast LDS.64 (no reg array).
// ---------------------------------------------------------------------------
__global__ void __launch_bounds__(128, 4) dw_kernel(const float* __restrict__ s) {
    const int bc0 = blockIdx.x * 2;
    __shared__ __align__(16) float sm[2][64 * 64];   // padded planes, row stride 64
    __shared__ ull wsm[2][KK2];
    const int t = threadIdx.x;

    // weight prepack (packed pairs for fma2)
    if (t < 2 * KK2) {
        const int pl = t / KK2;
        const int k = t - pl * KK2;
        const float w = g_wk[(size_t)(bc0 + pl) * KK2 + k];
        wsm[pl][k] = pack2(w, w);
    }

    // cooperative load of both planes (zero-padded borders), all-shift indexing
    for (int i = t; i < 2 * 64 * 64; i += 128) {
        const int pl = i >> 12;
        const int j = i & 4095;
        const int yy = j >> 6, xx = j & 63;
        const int y = yy - 3, x = xx - 3;
        float v = 0.f;
        if ((unsigned)y < 56u && (unsigned)x < 56u)
            v = s[(size_t)(bc0 + pl) * HWSZ + y * WW + x];
        sm[pl][yy * 64 + xx] = v;
    }
    __syncthreads();

    if (t >= 112) return;
    const int pl = t / 56;
    const int v = t - pl * 56;
    const int ytile = v / 7;
    const int xtile = v - ytile * 7;
    const int y0 = ytile * 7;
    const int x0 = xtile * 8;
    const float* __restrict__ smp = sm[pl];
    const ull* __restrict__ wp = wsm[pl];
    float* __restrict__ out = g_scratch + (size_t)(bc0 + pl) * HWSZ;

    ull acc[7][4];
    #pragma unroll
    for (int oy = 0; oy < 7; oy++)
        #pragma unroll
        for (int j = 0; j < 4; j++) acc[oy][j] = 0ull;

    #pragma unroll
    for (int r = 0; r < 13; r++) {
        const float* row = &smp[(y0 + r) * 64 + x0];
        const float4 q0 = *reinterpret_cast<const float4*>(row);
        const float4 q1 = *reinterpret_cast<const float4*>(row + 4);
        const float4 q2 = *reinterpret_cast<const float4*>(row + 8);
        const float4 q3 = *reinterpret_cast<const float4*>(row + 12);
        const float f[16] = {q0.x, q0.y, q0.z, q0.w, q1.x, q1.y, q1.z, q1.w,
                             q2.x, q2.y, q2.z, q2.w, q3.x, q3.y, q3.z, q3.w};
        ull p[13];
        #pragma unroll
        for (int i = 0; i < 13; i++) p[i] = pack2(f[i], f[i + 1]);

        #pragma unroll
        for (int oy = 0; oy < 7; oy++) {
            const int ky = r - oy;
            if (ky >= 0 && ky < 7) {
                #pragma unroll
                for (int kx = 0; kx < 7; kx++) {
                    const ull w = wp[ky * 7 + kx];
                    fma2(acc[oy][0], w, p[kx]);
                    fma2(acc[oy][1], w, p[kx + 2]);
                    fma2(acc[oy][2], w, p[kx + 4]);
                    fma2(acc[oy][3], w, p[kx + 6]);
                }
            }
        }
    }

    #pragma unroll
    for (int oy = 0; oy < 7; oy++) {
        const float2 v0 = unpack2(acc[oy][0]);
        const float2 v1 = unpack2(acc[oy][1]);
        const float2 v2 = unpack2(acc[oy][2]);
        const float2 v3 = unpack2(acc[oy][3]);
        float4 o0, o1;
        o0.x = gelu_f(v0.x); o0.y = gelu_f(v0.y); o0.z = gelu_f(v1.x); o0.w = gelu_f(v1.y);
        o1.x = gelu_f(v2.x); o1.y = gelu_f(v2.y); o1.z = gelu_f(v3.x); o1.w = gelu_f(v3.y);
        float* orow = out + (y0 + oy) * WW + x0;
        *reinterpret_cast<float4*>(orow) = o0;
        *reinterpret_cast<float4*>(orow + 4) = o1;
    }
}

// ---------------------------------------------------------------------------
// Kernel 4: pointwise conv as SGEMM over flattened n = b*3136 + p
// Block: 512 threads, tile 128(d) x 256(n), 8x8 per thread, K-step 8,
// double-buffered, packed f32x2 FMA. A-fragments broadcast per warp.
// ---------------------------------------------------------------------------
__global__ void __launch_bounds__(512, 1) pw_gemm_kernel(const float* __restrict__ A,
                                                         const float* __restrict__ bias,
                                                         float* __restrict__ out) {
    __shared__ __align__(16) float As[2][8][128];
    __shared__ __align__(16) float Bs[2][8][256];

    const int t = threadIdx.x;
    const int n0 = blockIdx.x * 256;
    const int dBase = blockIdx.y * 128;

    const int a_d = (t & 255) >> 1;     // 0..127 (only t<256 loads A)
    const int a_k = (t & 1) * 4;        // 0 or 4
    const int b_c = t >> 6;             // 0..7
    const int b_o = (t & 63) * 4;       // 0..252

    // per-thread B pointer: n -> (batch, p); float4 never crosses batch (4|3136)
    const int n_t = n0 + b_o;
    const int bt = n_t / HWSZ;
    const float* __restrict__ Bg = g_scratch + (size_t)bt * CC * HWSZ + (n_t - bt * HWSZ);
    const float* __restrict__ Ag = A + (size_t)(dBase + a_d) * CC + a_k;

    // prologue: tile 0
    {
        const float4 bv = *reinterpret_cast<const float4*>(Bg + (size_t)b_c * HWSZ);
        *reinterpret_cast<float4*>(&Bs[0][b_c][b_o]) = bv;
        if (t < 256) {
            const float4 av = *reinterpret_cast<const float4*>(Ag);
            As[0][a_k + 0][a_d] = av.x;
            As[0][a_k + 1][a_d] = av.y;
            As[0][a_k + 2][a_d] = av.z;
            As[0][a_k + 3][a_d] = av.w;
        }
    }

    ull acc[8][4];
    #pragma unroll
    for (int i = 0; i < 8; i++)
        #pragma unroll
        for (int j = 0; j < 4; j++) acc[i][j] = 0ull;

    const int tx = t & 31;   // n sub-tile (8 contiguous floats)
    const int ty = t >> 5;   // d sub-tile == warp id -> A fragment broadcast

    const int NKT = CC / 8;  // 32 k-tiles
    for (int kt = 0; kt < NKT; kt++) {
        __syncthreads();
        const int cur = kt & 1;

        float4 av2, bv2;
        const bool more = (kt + 1) < NKT;
        if (more) {
            const int k0 = (kt + 1) * 8;
            bv2 = *reinterpret_cast<const float4*>(Bg + (size_t)(k0 + b_c) * HWSZ);
            if (t < 256) av2 = *reinterpret_cast<const float4*>(Ag + k0);
        }

        #pragma unroll
        for (int k = 0; k < 8; k++) {
            const float4 aq0 = *reinterpret_cast<const float4*>(&As[cur][k][ty * 8]);
            const float4 aq1 = *reinterpret_cast<const float4*>(&As[cur][k][ty * 8 + 4]);
            const float4 bq0 = *reinterpret_cast<const float4*>(&Bs[cur][k][tx * 8]);
            const float4 bq1 = *reinterpret_cast<const float4*>(&Bs[cur][k][tx * 8 + 4]);

            ull bp[4];
            bp[0] = pack2(bq0.x, bq0.y);
            bp[1] = pack2(bq0.z, bq0.w);
            bp[2] = pack2(bq1.x, bq1.y);
            bp[3] = pack2(bq1.z, bq1.w);

            const float aa[8] = {aq0.x, aq0.y, aq0.z, aq0.w, aq1.x, aq1.y, aq1.z, aq1.w};
            #pragma unroll
            for (int i = 0; i < 8; i++) {
                const ull ap = pack2(aa[i], aa[i]);
                #pragma unroll
                for (int j = 0; j < 4; j++) fma2(acc[i][j], ap, bp[j]);
            }
        }

        if (more) {
            const int nxt = 1 - cur;
            *reinterpret_cast<float4*>(&Bs[nxt][b_c][b_o]) = bv2;
            if (t < 256) {
                As[nxt][a_k + 0][a_d] = av2.x;
                As[nxt][a_k + 1][a_d] = av2.y;
                As[nxt][a_k + 2][a_d] = av2.z;
                As[nxt][a_k + 3][a_d] = av2.w;
            }
        }
    }

    // epilogue: add bias, store. 8 contiguous n per thread (8 | 3136: no
    // batch crossing within a thread's fragment).
    const int n_g = n0 + tx * 8;
    const int bq = n_g / HWSZ;
    const int pq = n_g - bq * HWSZ;
    #pragma unroll
    for (int i = 0; i < 8; i++) {
        const int d = dBase + ty * 8 + i;
        const float bb = bias[d];
        const float2 v0 = unpack2(acc[i][0]);
        const float2 v1 = unpack2(acc[i][1]);
        const float2 v2 = unpack2(acc[i][2]);
        const float2 v3 = unpack2(acc[i][3]);
        float4 o0, o1;
        o0.x = v0.x + bb; o0.y = v0.y + bb; o0.z = v1.x + bb; o0.w = v1.y + bb;
        o1.x = v2.x + bb; o1.y = v2.y + bb; o1.z = v3.x + bb; o1.w = v3.y + bb;
        float* orow = out + ((size_t)bq * CC + d) * HWSZ + pq;
        *reinterpret_cast<float4*>(orow) = o0;
        *reinterpret_cast<float4*>(orow + 4) = o1;
    }
}

// ---------------------------------------------------------------------------
// launch
// ---------------------------------------------------------------------------
extern "C" void kernel_launch(void* const* d_in, const int* in_sizes, int n_in,
                              void* d_out, int out_size) {
    (void)in_sizes; (void)n_in; (void)out_size;
    const float* s      = (const float*)d_in[0];
    const float* r      = (const float*)d_in[1];
    const float* pw1    = (const float*)d_in[2];
    const float* pb1    = (const float*)d_in[3];
    const float* pw2    = (const float*)d_in[4];
    const float* pb2    = (const float*)d_in[5];
    const float* weight = (const float*)d_in[6];
    const float* bscale = (const float*)d_in[7];
    const float* pww    = (const float*)d_in[8];
    const float* pwb    = (const float*)d_in[9];
    float* out = (float*)d_out;

    pool_kernel<<<BB * CC, 256>>>(r);
    wgen_kernel<<<BB, 256>>>(pw1, pb1, pw2, pb2, weight, bscale);
    dw_kernel<<<BB * CC / 2, 128>>>(s);
    dim3 grid(NTOT / 256, CC / 128, 1);
    pw_gemm_kernel<<<grid, 512>>>(pww, pwb, out);
}

// round 4
// speedup vs baseline: 1.0922x; 1.0922x over previous
#include <cuda_runtime.h>
#include <cstdint>
#include <cstddef>

// Problem constants
#define BB   32
#define CC   256
#define HH   56
#define WW   56
#define HWSZ 3136          // 56*56
#define GG   4
#define KS   7
#define KK2  49            // 7*7
#define CRR  64            // C / 4
#define NTOT (BB * HWSZ)   // 100352 = 392 * 256

typedef unsigned long long ull;

// Scratch (device globals: allocation-free per harness rules)
__device__ float g_scratch[(size_t)BB * CC * HWSZ];   // gelu(dwconv(s)) : ~103 MB
__device__ float g_pooled[BB * CC];
__device__ float g_wk[(size_t)BB * CC * KK2];         // per-(b,c) 7x7 kernels

// ---------------------------------------------------------------------------
// helpers
// ---------------------------------------------------------------------------
__device__ __forceinline__ float gelu_f(float x) {
    return 0.5f * x * (1.0f + erff(x * 0.70710678118654752440f));
}
__device__ __forceinline__ ull pack2(float lo, float hi) {
    ull r; asm("mov.b64 %0, {%1, %2};" : "=l"(r) : "f"(lo), "f"(hi)); return r;
}
__device__ __forceinline__ void fma2(ull& d, ull a, ull b) {
    asm("fma.rn.f32x2 %0, %1, %2, %0;" : "+l"(d) : "l"(a), "l"(b));
}
__device__ __forceinline__ float2 unpack2(ull v) {
    float2 r; asm("mov.b64 {%0, %1}, %2;" : "=f"(r.x), "=f"(r.y) : "l"(v)); return r;
}

// ---------------------------------------------------------------------------
// Kernel 1: pooled[b,c] = mean over H,W of r
// ---------------------------------------------------------------------------
__global__ void pool_kernel(const float* __restrict__ r) {
    const int bc = blockIdx.x;
    const float4* p = reinterpret_cast<const float4*>(r + (size_t)bc * HWSZ);
    float s = 0.f;
    #pragma unroll 4
    for (int i = threadIdx.x; i < HWSZ / 4; i += 256) {
        float4 v = p[i];
        s += (v.x + v.y) + (v.z + v.w);
    }
    __shared__ float red[8];
    #pragma unroll
    for (int o = 16; o > 0; o >>= 1) s += __shfl_down_sync(0xFFFFFFFFu, s, o);
    if ((threadIdx.x & 31) == 0) red[threadIdx.x >> 5] = s;
    __syncthreads();
    if (threadIdx.x < 8) {
        s = red[threadIdx.x];
        #pragma unroll
        for (int o = 4; o > 0; o >>= 1) s += __shfl_down_sync(0xFFu, s, o);
        if (threadIdx.x == 0) g_pooled[bc] = s * (1.0f / (float)HWSZ);
    }
}

// ---------------------------------------------------------------------------
// Kernel 2: SE weight generation -> g_wk[b,c,49]
// ---------------------------------------------------------------------------
__global__ void wgen_kernel(const float* __restrict__ w1, const float* __restrict__ b1,
                            const float* __restrict__ w2, const float* __restrict__ b2,
                            const float* __restrict__ weight, const float* __restrict__ bscale) {
    const int b = blockIdx.x;
    const int t = threadIdx.x;
    __shared__ float ps[CC];
    __shared__ float hs[CRR];

    ps[t] = g_pooled[b * CC + t];
    __syncthreads();

    if (t < CRR) {
        float acc = b1[t];
        const float* wr = w1 + (size_t)t * CC;
        #pragma unroll 4
        for (int c = 0; c < CC; c++) acc = fmaf(ps[c], wr[c], acc);
        hs[t] = gelu_f(acc);
    }
    __syncthreads();

    float vals[GG][2];
    #pragma unroll
    for (int g = 0; g < GG; g++) {
        #pragma unroll
        for (int e = 0; e < 2; e++) {
            const int row = (g * CC + t) * 2 + e;
            float acc = b2[row];
            const float* wr = w2 + (size_t)row * CRR;
            #pragma unroll 4
            for (int k = 0; k < CRR; k++) acc = fmaf(hs[k], wr[k], acc);
            vals[g][e] = acc;
        }
    }

    float m = fmaxf(fmaxf(vals[0][0], vals[1][0]), fmaxf(vals[2][0], vals[3][0]));
    float alpha[GG];
    float ssum = 0.f;
    #pragma unroll
    for (int g = 0; g < GG; g++) { alpha[g] = expf(vals[g][0] - m); ssum += alpha[g]; }
    const float inv = 1.0f / ssum;
    float betasum = 0.f;
    #pragma unroll
    for (int g = 0; g < GG; g++) {
        alpha[g] *= inv;
        betasum += tanhf(vals[g][1] * expf(bscale[g * CC + t]) * 0.1f);
    }

    float* out = g_wk + ((size_t)b * CC + t) * KK2;
    #pragma unroll
    for (int k = 0; k < KK2; k++) {
        float acc = betasum;
        #pragma unroll
        for (int g = 0; g < GG; g++)
            acc = fmaf(alpha[g], weight[((size_t)g * CC + t) * KK2 + k], acc);
        out[k] = acc;
    }
}

// ---------------------------------------------------------------------------
// Kernel 3: dynamic depthwise 7x7 conv (pad 3) + exact GELU -> g_scratch
// 2 planes per 256-thread block, 196 active compute threads (98 per plane).
// Per-thread tile 4(y) x 8(x): acc = 16 ull = 32 regs -> no spills under
// the 128-reg cap of launch_bounds(256,2).
// ---------------------------------------------------------------------------
__global__ void __launch_bounds__(256, 2) dw_kernel(const float* __restrict__ s) {
    const int bc0 = blockIdx.x * 2;
    __shared__ __align__(16) float sm[2][62 * 64];   // padded planes, row stride 64
    __shared__ ull wsm[2][KK2];
    const int t = threadIdx.x;

    // weight prepack (packed (w,w) pairs for fma2)
    if (t < 2 * KK2) {
        const int pl = t / KK2;
        const int k = t - pl * KK2;
        const float w = g_wk[(size_t)(bc0 + pl) * KK2 + k];
        wsm[pl][k] = pack2(w, w);
    }

    // cooperative load of both planes (zero-padded borders)
    for (int i = t; i < 2 * 62 * 64; i += 256) {
        const int pl = i / (62 * 64);
        const int j = i - pl * (62 * 64);
        const int yy = j >> 6, xx = j & 63;
        const int y = yy - 3, x = xx - 3;
        float v = 0.f;
        if ((unsigned)y < 56u && (unsigned)x < 56u)
            v = s[(size_t)(bc0 + pl) * HWSZ + y * WW + x];
        sm[pl][yy * 64 + xx] = v;
    }
    __syncthreads();

    if (t >= 196) return;
    const int pl = t / 98;
    const int v = t - pl * 98;
    const int ytile = v / 7;            // 0..13
    const int xtile = v - ytile * 7;    // 0..6
    const int y0 = ytile * 4;
    const int x0 = xtile * 8;
    const float* __restrict__ smp = sm[pl];
    const ull* __restrict__ wp = wsm[pl];
    float* __restrict__ out = g_scratch + (size_t)(bc0 + pl) * HWSZ;

    ull acc[4][4];
    #pragma unroll
    for (int oy = 0; oy < 4; oy++)
        #pragma unroll
        for (int j = 0; j < 4; j++) acc[oy][j] = 0ull;

    #pragma unroll
    for (int r = 0; r < 10; r++) {
        const float* row = &smp[(y0 + r) * 64 + x0];
        const float4 q0 = *reinterpret_cast<const float4*>(row);
        const float4 q1 = *reinterpret_cast<const float4*>(row + 4);
        const float4 q2 = *reinterpret_cast<const float4*>(row + 8);
        const float4 q3 = *reinterpret_cast<const float4*>(row + 12);
        const float f[16] = {q0.x, q0.y, q0.z, q0.w, q1.x, q1.y, q1.z, q1.w,
                             q2.x, q2.y, q2.z, q2.w, q3.x, q3.y, q3.z, q3.w};
        ull p[13];
        #pragma unroll
        for (int i = 0; i < 13; i++) p[i] = pack2(f[i], f[i + 1]);

        #pragma unroll
        for (int oy = 0; oy < 4; oy++) {
            const int ky = r - oy;
            if (ky >= 0 && ky < 7) {
                #pragma unroll
                for (int kx = 0; kx < 7; kx++) {
                    const ull w = wp[ky * 7 + kx];
                    fma2(acc[oy][0], w, p[kx]);
                    fma2(acc[oy][1], w, p[kx + 2]);
                    fma2(acc[oy][2], w, p[kx + 4]);
                    fma2(acc[oy][3], w, p[kx + 6]);
                }
            }
        }
    }

    #pragma unroll
    for (int oy = 0; oy < 4; oy++) {
        const float2 v0 = unpack2(acc[oy][0]);
        const float2 v1 = unpack2(acc[oy][1]);
        const float2 v2 = unpack2(acc[oy][2]);
        const float2 v3 = unpack2(acc[oy][3]);
        float4 o0, o1;
        o0.x = gelu_f(v0.x); o0.y = gelu_f(v0.y); o0.z = gelu_f(v1.x); o0.w = gelu_f(v1.y);
        o1.x = gelu_f(v2.x); o1.y = gelu_f(v2.y); o1.z = gelu_f(v3.x); o1.w = gelu_f(v3.y);
        float* orow = out + (y0 + oy) * WW + x0;
        *reinterpret_cast<float4*>(orow) = o0;
        *reinterpret_cast<float4*>(orow + 4) = o1;
    }
}

// ---------------------------------------------------------------------------
// Kernel 4: pointwise conv as SGEMM over flattened n = b*3136 + p
// 256 threads, tile 128(d) x 256(n), per-thread 16(d) x 8(n), K-step 8,
// double-buffered. Zero-pack inner loop:
//   - A stored in smem pre-duplicated as (a,a) ull -> LDS.64 broadcast
//   - B fragments read directly as packed ull via LDS.128
// grid = (392, 2). 100352 = 392*256, no tail.
// ---------------------------------------------------------------------------
__global__ void __launch_bounds__(256, 1) pw_gemm_kernel(const float* __restrict__ A,
                                                         const float* __restrict__ bias,
                                                         float* __restrict__ out) {
    __shared__ __align__(16) ull  Asp[2][8][128];   // duplicated (a,a) pairs
    __shared__ __align__(16) float Bs[2][8][256];

    const int t = threadIdx.x;
    const int n0 = blockIdx.x * 256;
    const int dBase = blockIdx.y * 128;

    // global-load assignments
    const int a_d = t >> 1;             // 0..127
    const int a_k = (t & 1) * 4;        // 0 or 4
    const int b_c = t >> 5;             // 0..7
    const int b_o = (t & 31) * 4;       // 0..124

    // two B segments (cols b_o and b_o+128), batch-resolved pointers
    const int n_a = n0 + b_o;
    const int n_b = n_a + 128;
    const int ba = n_a / HWSZ;
    const int bbx = n_b / HWSZ;
    const float* __restrict__ Bga = g_scratch + (size_t)ba * CC * HWSZ + (n_a - ba * HWSZ);
    const float* __restrict__ Bgb = g_scratch + (size_t)bbx * CC * HWSZ + (n_b - bbx * HWSZ);
    const float* __restrict__ Ag = A + (size_t)(dBase + a_d) * CC + a_k;

    // prologue: tile 0
    {
        const float4 av = *reinterpret_cast<const float4*>(Ag);
        const float4 bv0 = *reinterpret_cast<const float4*>(Bga + (size_t)b_c * HWSZ);
        const float4 bv1 = *reinterpret_cast<const float4*>(Bgb + (size_t)b_c * HWSZ);
        Asp[0][a_k + 0][a_d] = pack2(av.x, av.x);
        Asp[0][a_k + 1][a_d] = pack2(av.y, av.y);
        Asp[0][a_k + 2][a_d] = pack2(av.z, av.z);
        Asp[0][a_k + 3][a_d] = pack2(av.w, av.w);
        *reinterpret_cast<float4*>(&Bs[0][b_c][b_o]) = bv0;
        *reinterpret_cast<float4*>(&Bs[0][b_c][b_o + 128]) = bv1;
    }

    ull acc[16][4];
    #pragma unroll
    for (int i = 0; i < 16; i++)
        #pragma unroll
        for (int j = 0; j < 4; j++) acc[i][j] = 0ull;

    const int tx = t & 31;   // n sub-tile: segments tx*4 and tx*4+128
    const int ty = t >> 5;   // d sub-tile (16 rows) == warp id -> A broadcast

    const int NKT = CC / 8;  // 32 k-tiles
    for (int kt = 0; kt < NKT; kt++) {
        __syncthreads();
        const int cur = kt & 1;

        float4 av2, bv20, bv21;
        const bool more = (kt + 1) < NKT;
        if (more) {
            const int k0 = (kt + 1) * 8;
            av2 = *reinterpret_cast<const float4*>(Ag + k0);
            bv20 = *reinterpret_cast<const float4*>(Bga + (size_t)(k0 + b_c) * HWSZ);
            bv21 = *reinterpret_cast<const float4*>(Bgb + (size_t)(k0 + b_c) * HWSZ);
        }

        #pragma unroll
        for (int k = 0; k < 8; k++) {
            // B: two LDS.128, each yields 2 packed (lo,hi) ulls
            const ulonglong2 bq0 =
                *reinterpret_cast<const ulonglong2*>(&Bs[cur][k][tx * 4]);
            const ulonglong2 bq1 =
                *reinterpret_cast<const ulonglong2*>(&Bs[cur][k][tx * 4 + 128]);
            const ull bp0 = bq0.x, bp1 = bq0.y, bp2 = bq1.x, bp3 = bq1.y;

            const ull* arow = &Asp[cur][k][ty * 16];
            #pragma unroll
            for (int i = 0; i < 16; i++) {
                const ull ap = arow[i];      // broadcast LDS.64, pre-duplicated
                fma2(acc[i][0], ap, bp0);
                fma2(acc[i][1], ap, bp1);
                fma2(acc[i][2], ap, bp2);
                fma2(acc[i][3], ap, bp3);
            }
        }

        if (more) {
            const int nxt = 1 - cur;
            Asp[nxt][a_k + 0][a_d] = pack2(av2.x, av2.x);
            Asp[nxt][a_k + 1][a_d] = pack2(av2.y, av2.y);
            Asp[nxt][a_k + 2][a_d] = pack2(av2.z, av2.z);
            Asp[nxt][a_k + 3][a_d] = pack2(av2.w, av2.w);
            *reinterpret_cast<float4*>(&Bs[nxt][b_c][b_o]) = bv20;
            *reinterpret_cast<float4*>(&Bs[nxt][b_c][b_o + 128]) = bv21;
        }
    }

    // epilogue: add bias, store. Segments: n0+tx*4 and n0+tx*4+128.
    // 4 | 3136 so a float4 never crosses a batch boundary.
    const int n_s0 = n0 + tx * 4;
    const int n_s1 = n_s0 + 128;
    const int bq0i = n_s0 / HWSZ;
    const int bq1i = n_s1 / HWSZ;
    const int pq0 = n_s0 - bq0i * HWSZ;
    const int pq1 = n_s1 - bq1i * HWSZ;
    #pragma unroll
    for (int i = 0; i < 16; i++) {
        const int d = dBase + ty * 16 + i;
        const float bb = bias[d];
        const float2 v0 = unpack2(acc[i][0]);
        const float2 v1 = unpack2(acc[i][1]);
        const float2 v2 = unpack2(acc[i][2]);
        const float2 v3 = unpack2(acc[i][3]);
        float4 o0, o1;
        o0.x = v0.x + bb; o0.y = v0.y + bb; o0.z = v1.x + bb; o0.w = v1.y + bb;
        o1.x = v2.x + bb; o1.y = v2.y + bb; o1.z = v3.x + bb; o1.w = v3.y + bb;
        *reinterpret_cast<float4*>(out + ((size_t)bq0i * CC + d) * HWSZ + pq0) = o0;
        *reinterpret_cast<float4*>(out + ((size_t)bq1i * CC + d) * HWSZ + pq1) = o1;
    }
}

// ---------------------------------------------------------------------------
// launch
// ---------------------------------------------------------------------------
extern "C" void kernel_launch(void* const* d_in, const int* in_sizes, int n_in,
                              void* d_out, int out_size) {
    (void)in_sizes; (void)n_in; (void)out_size;
    const float* s      = (const float*)d_in[0];
    const float* r      = (const float*)d_in[1];
    const float* pw1    = (const float*)d_in[2];
    const float* pb1    = (const float*)d_in[3];
    const float* pw2    = (const float*)d_in[4];
    const float* pb2    = (const float*)d_in[5];
    const float* weight = (const float*)d_in[6];
    const float* bscale = (const float*)d_in[7];
    const float* pww    = (const float*)d_in[8];
    const float* pwb    = (const float*)d_in[9];
    float* out = (float*)d_out;

    pool_kernel<<<BB * CC, 256>>>(r);
    wgen_kernel<<<BB, 256>>>(pw1, pb1, pw2, pb2, weight, bscale);
    dw_kernel<<<BB * CC / 2, 256>>>(s);
    dim3 grid(NTOT / 256, CC / 128, 1);
    pw_gemm_kernel<<<grid, 256>>>(pww, pwb, out);
}

// round 5
// speedup vs baseline: 1.1071x; 1.0137x over previous
#include <cuda_runtime.h>
#include <cstdint>
#include <cstddef>

// Problem constants
#define BB   32
#define CC   256
#define HH   56
#define WW   56
#define HWSZ 3136          // 56*56
#define GG   4
#define KS   7
#define KK2  49            // 7*7
#define CRR  64            // C / 4
#define NTOT (BB * HWSZ)   // 100352 = 784 * 128

typedef unsigned long long ull;

// Scratch (device globals: allocation-free per harness rules)
__device__ float g_scratch[(size_t)BB * CC * HWSZ];   // gelu(dwconv(s)) : ~103 MB
__device__ float g_pooled[BB * CC];
__device__ float g_wk[(size_t)BB * CC * KK2];         // per-(b,c) 7x7 kernels

// ---------------------------------------------------------------------------
// helpers
// ---------------------------------------------------------------------------
__device__ __forceinline__ float gelu_f(float x) {
    return 0.5f * x * (1.0f + erff(x * 0.70710678118654752440f));
}
__device__ __forceinline__ ull pack2(float lo, float hi) {
    ull r; asm("mov.b64 %0, {%1, %2};" : "=l"(r) : "f"(lo), "f"(hi)); return r;
}
__device__ __forceinline__ void fma2(ull& d, ull a, ull b) {
    asm("fma.rn.f32x2 %0, %1, %2, %0;" : "+l"(d) : "l"(a), "l"(b));
}
__device__ __forceinline__ float2 unpack2(ull v) {
    float2 r; asm("mov.b64 {%0, %1}, %2;" : "=f"(r.x), "=f"(r.y) : "l"(v)); return r;
}
__device__ __forceinline__ float4 ldcs4(const float* p) {
    float4 v;
    asm("ld.global.cs.v4.f32 {%0,%1,%2,%3}, [%4];"
        : "=f"(v.x), "=f"(v.y), "=f"(v.z), "=f"(v.w) : "l"(p));
    return v;
}
__device__ __forceinline__ void stcs4(float* p, float4 v) {
    asm("st.global.cs.v4.f32 [%0], {%1,%2,%3,%4};"
        :: "l"(p), "f"(v.x), "f"(v.y), "f"(v.z), "f"(v.w));
}

// ---------------------------------------------------------------------------
// Kernel 1: pooled[b,c] = mean over H,W of r  (r read streaming: used once)
// ---------------------------------------------------------------------------
__global__ void pool_kernel(const float* __restrict__ r) {
    const int bc = blockIdx.x;
    const float* p = r + (size_t)bc * HWSZ;
    float s = 0.f;
    #pragma unroll 4
    for (int i = threadIdx.x; i < HWSZ / 4; i += 256) {
        float4 v = ldcs4(p + i * 4);
        s += (v.x + v.y) + (v.z + v.w);
    }
    __shared__ float red[8];
    #pragma unroll
    for (int o = 16; o > 0; o >>= 1) s += __shfl_down_sync(0xFFFFFFFFu, s, o);
    if ((threadIdx.x & 31) == 0) red[threadIdx.x >> 5] = s;
    __syncthreads();
    if (threadIdx.x < 8) {
        s = red[threadIdx.x];
        #pragma unroll
        for (int o = 4; o > 0; o >>= 1) s += __shfl_down_sync(0xFFu, s, o);
        if (threadIdx.x == 0) g_pooled[bc] = s * (1.0f / (float)HWSZ);
    }
}

// ---------------------------------------------------------------------------
// Kernel 2: SE weight generation -> g_wk[b,c,49]
// ---------------------------------------------------------------------------
__global__ void wgen_kernel(const float* __restrict__ w1, const float* __restrict__ b1,
                            const float* __restrict__ w2, const float* __restrict__ b2,
                            const float* __restrict__ weight, const float* __restrict__ bscale) {
    const int b = blockIdx.x;
    const int t = threadIdx.x;
    __shared__ float ps[CC];
    __shared__ float hs[CRR];

    ps[t] = g_pooled[b * CC + t];
    __syncthreads();

    if (t < CRR) {
        float acc = b1[t];
        const float* wr = w1 + (size_t)t * CC;
        #pragma unroll 4
        for (int c = 0; c < CC; c++) acc = fmaf(ps[c], wr[c], acc);
        hs[t] = gelu_f(acc);
    }
    __syncthreads();

    float vals[GG][2];
    #pragma unroll
    for (int g = 0; g < GG; g++) {
        #pragma unroll
        for (int e = 0; e < 2; e++) {
            const int row = (g * CC + t) * 2 + e;
            float acc = b2[row];
            const float* wr = w2 + (size_t)row * CRR;
            #pragma unroll 4
            for (int k = 0; k < CRR; k++) acc = fmaf(hs[k], wr[k], acc);
            vals[g][e] = acc;
        }
    }

    float m = fmaxf(fmaxf(vals[0][0], vals[1][0]), fmaxf(vals[2][0], vals[3][0]));
    float alpha[GG];
    float ssum = 0.f;
    #pragma unroll
    for (int g = 0; g < GG; g++) { alpha[g] = expf(vals[g][0] - m); ssum += alpha[g]; }
    const float inv = 1.0f / ssum;
    float betasum = 0.f;
    #pragma unroll
    for (int g = 0; g < GG; g++) {
        alpha[g] *= inv;
        betasum += tanhf(vals[g][1] * expf(bscale[g * CC + t]) * 0.1f);
    }

    float* out = g_wk + ((size_t)b * CC + t) * KK2;
    #pragma unroll
    for (int k = 0; k < KK2; k++) {
        float acc = betasum;
        #pragma unroll
        for (int g = 0; g < GG; g++)
            acc = fmaf(alpha[g], weight[((size_t)g * CC + t) * KK2 + k], acc);
        out[k] = acc;
    }
}

// ---------------------------------------------------------------------------
// Kernel 3: dynamic depthwise 7x7 conv (pad 3) + exact GELU -> g_scratch
// (unchanged from R4; s read streaming — used once)
// ---------------------------------------------------------------------------
__global__ void __launch_bounds__(256, 2) dw_kernel(const float* __restrict__ s) {
    const int bc0 = blockIdx.x * 2;
    __shared__ __align__(16) float sm[2][62 * 64];   // padded planes, row stride 64
    __shared__ ull wsm[2][KK2];
    const int t = threadIdx.x;

    if (t < 2 * KK2) {
        const int pl = t / KK2;
        const int k = t - pl * KK2;
        const float w = g_wk[(size_t)(bc0 + pl) * KK2 + k];
        wsm[pl][k] = pack2(w, w);
    }

    for (int i = t; i < 2 * 62 * 64; i += 256) {
        const int pl = i / (62 * 64);
        const int j = i - pl * (62 * 64);
        const int yy = j >> 6, xx = j & 63;
        const int y = yy - 3, x = xx - 3;
        float v = 0.f;
        if ((unsigned)y < 56u && (unsigned)x < 56u)
            v = __ldcs(s + (size_t)(bc0 + pl) * HWSZ + y * WW + x);
        sm[pl][yy * 64 + xx] = v;
    }
    __syncthreads();

    if (t >= 196) return;
    const int pl = t / 98;
    const int v = t - pl * 98;
    const int ytile = v / 7;            // 0..13
    const int xtile = v - ytile * 7;    // 0..6
    const int y0 = ytile * 4;
    const int x0 = xtile * 8;
    const float* __restrict__ smp = sm[pl];
    const ull* __restrict__ wp = wsm[pl];
    float* __restrict__ out = g_scratch + (size_t)(bc0 + pl) * HWSZ;

    ull acc[4][4];
    #pragma unroll
    for (int oy = 0; oy < 4; oy++)
        #pragma unroll
        for (int j = 0; j < 4; j++) acc[oy][j] = 0ull;

    #pragma unroll
    for (int r = 0; r < 10; r++) {
        const float* row = &smp[(y0 + r) * 64 + x0];
        const float4 q0 = *reinterpret_cast<const float4*>(row);
        const float4 q1 = *reinterpret_cast<const float4*>(row + 4);
        const float4 q2 = *reinterpret_cast<const float4*>(row + 8);
        const float4 q3 = *reinterpret_cast<const float4*>(row + 12);
        const float f[16] = {q0.x, q0.y, q0.z, q0.w, q1.x, q1.y, q1.z, q1.w,
                             q2.x, q2.y, q2.z, q2.w, q3.x, q3.y, q3.z, q3.w};
        ull p[13];
        #pragma unroll
        for (int i = 0; i < 13; i++) p[i] = pack2(f[i], f[i + 1]);

        #pragma unroll
        for (int oy = 0; oy < 4; oy++) {
            const int ky = r - oy;
            if (ky >= 0 && ky < 7) {
                #pragma unroll
                for (int kx = 0; kx < 7; kx++) {
                    const ull w = wp[ky * 7 + kx];
                    fma2(acc[oy][0], w, p[kx]);
                    fma2(acc[oy][1], w, p[kx + 2]);
                    fma2(acc[oy][2], w, p[kx + 4]);
                    fma2(acc[oy][3], w, p[kx + 6]);
                }
            }
        }
    }

    #pragma unroll
    for (int oy = 0; oy < 4; oy++) {
        const float2 v0 = unpack2(acc[oy][0]);
        const float2 v1 = unpack2(acc[oy][1]);
        const float2 v2 = unpack2(acc[oy][2]);
        const float2 v3 = unpack2(acc[oy][3]);
        float4 o0, o1;
        o0.x = gelu_f(v0.x); o0.y = gelu_f(v0.y); o0.z = gelu_f(v1.x); o0.w = gelu_f(v1.y);
        o1.x = gelu_f(v2.x); o1.y = gelu_f(v2.y); o1.z = gelu_f(v3.x); o1.w = gelu_f(v3.y);
        float* orow = out + (y0 + oy) * WW + x0;
        *reinterpret_cast<float4*>(orow) = o0;
        *reinterpret_cast<float4*>(orow + 4) = o1;
    }
}

// ---------------------------------------------------------------------------
// Kernel 4: pointwise conv as SGEMM over flattened n = b*3136 + p
// 256 threads, tile 128(d) x 128(n), per-thread 8(d) x 8(n) -> acc 64 regs,
// TWO blocks per SM (16 warps: real latency hiding). K-step 8, double
// buffered. A pre-duplicated (a,a) ull in smem; B read as packed ull.
// out written with st.cs (evict-first) to keep scratch L2-resident.
// grid = (784, 2). 100352 = 784*128, no tail.
// ---------------------------------------------------------------------------
__global__ void __launch_bounds__(256, 2) pw_gemm_kernel(const float* __restrict__ A,
                                                         const float* __restrict__ bias,
                                                         float* __restrict__ out) {
    __shared__ __align__(16) ull   Asp[2][8][128];   // duplicated (a,a) pairs, 16KB
    __shared__ __align__(16) float Bs[2][8][128];    // 8KB

    const int t = threadIdx.x;
    const int n0 = blockIdx.x * 128;
    const int dBase = blockIdx.y * 128;

    // global-load assignments
    const int a_d = t >> 1;             // 0..127
    const int a_k = (t & 1) * 4;        // 0 or 4
    const int b_c = t >> 5;             // 0..7
    const int b_o = (t & 31) * 4;       // 0..124

    // B pointer: n -> (batch, p); float4 never crosses batch (4 | 3136)
    const int n_t = n0 + b_o;
    const int bt = n_t / HWSZ;
    const float* __restrict__ Bg = g_scratch + (size_t)bt * CC * HWSZ + (n_t - bt * HWSZ);
    const float* __restrict__ Ag = A + (size_t)(dBase + a_d) * CC + a_k;

    // prologue: tile 0
    {
        const float4 av = *reinterpret_cast<const float4*>(Ag);
        const float4 bv = *reinterpret_cast<const float4*>(Bg + (size_t)b_c * HWSZ);
        Asp[0][a_k + 0][a_d] = pack2(av.x, av.x);
        Asp[0][a_k + 1][a_d] = pack2(av.y, av.y);
        Asp[0][a_k + 2][a_d] = pack2(av.z, av.z);
        Asp[0][a_k + 3][a_d] = pack2(av.w, av.w);
        *reinterpret_cast<float4*>(&Bs[0][b_c][b_o]) = bv;
    }

    ull acc[8][4];
    #pragma unroll
    for (int i = 0; i < 8; i++)
        #pragma unroll
        for (int j = 0; j < 4; j++) acc[i][j] = 0ull;

    const int tx = t & 15;   // n sub-tile: 8 contiguous floats at tx*8
    const int ty = t >> 4;   // d sub-tile: 8 rows at ty*8

    const int NKT = CC / 8;  // 32 k-tiles
    for (int kt = 0; kt < NKT; kt++) {
        __syncthreads();
        const int cur = kt & 1;

        float4 av2, bv2;
        const bool more = (kt + 1) < NKT;
        if (more) {
            const int k0 = (kt + 1) * 8;
            av2 = *reinterpret_cast<const float4*>(Ag + k0);
            bv2 = *reinterpret_cast<const float4*>(Bg + (size_t)(k0 + b_c) * HWSZ);
        }

        #pragma unroll
        for (int k = 0; k < 8; k++) {
            // B: 8 floats = 2 LDS.128 yielding 4 packed ulls
            const ulonglong2 bq0 =
                *reinterpret_cast<const ulonglong2*>(&Bs[cur][k][tx * 8]);
            const ulonglong2 bq1 =
                *reinterpret_cast<const ulonglong2*>(&Bs[cur][k][tx * 8 + 4]);
            const ull bp0 = bq0.x, bp1 = bq0.y, bp2 = bq1.x, bp3 = bq1.y;

            // A: 8 duplicated ulls = 4 LDS.128 (half-warp broadcast)
            const ulonglong2 aq0 =
                *reinterpret_cast<const ulonglong2*>(&Asp[cur][k][ty * 8]);
            const ulonglong2 aq1 =
                *reinterpret_cast<const ulonglong2*>(&Asp[cur][k][ty * 8 + 2]);
            const ulonglong2 aq2 =
                *reinterpret_cast<const ulonglong2*>(&Asp[cur][k][ty * 8 + 4]);
            const ulonglong2 aq3 =
                *reinterpret_cast<const ulonglong2*>(&Asp[cur][k][ty * 8 + 6]);
            const ull ap[8] = {aq0.x, aq0.y, aq1.x, aq1.y,
                               aq2.x, aq2.y, aq3.x, aq3.y};

            #pragma unroll
            for (int i = 0; i < 8; i++) {
                fma2(acc[i][0], ap[i], bp0);
                fma2(acc[i][1], ap[i], bp1);
                fma2(acc[i][2], ap[i], bp2);
                fma2(acc[i][3], ap[i], bp3);
            }
        }

        if (more) {
            const int nxt = 1 - cur;
            Asp[nxt][a_k + 0][a_d] = pack2(av2.x, av2.x);
            Asp[nxt][a_k + 1][a_d] = pack2(av2.y, av2.y);
            Asp[nxt][a_k + 2][a_d] = pack2(av2.z, av2.z);
            Asp[nxt][a_k + 3][a_d] = pack2(av2.w, av2.w);
            *reinterpret_cast<float4*>(&Bs[nxt][b_c][b_o]) = bv2;
        }
    }

    // epilogue: add bias, store with evict-first (8 | 3136: no batch crossing)
    const int n_g = n0 + tx * 8;
    const int bq = n_g / HWSZ;
    const int pq = n_g - bq * HWSZ;
    #pragma unroll
    for (int i = 0; i < 8; i++) {
        const int d = dBase + ty * 8 + i;
        const float bb = bias[d];
        const float2 v0 = unpack2(acc[i][0]);
        const float2 v1 = unpack2(acc[i][1]);
        const float2 v2 = unpack2(acc[i][2]);
        const float2 v3 = unpack2(acc[i][3]);
        float4 o0, o1;
        o0.x = v0.x + bb; o0.y = v0.y + bb; o0.z = v1.x + bb; o0.w = v1.y + bb;
        o1.x = v2.x + bb; o1.y = v2.y + bb; o1.z = v3.x + bb; o1.w = v3.y + bb;
        float* orow = out + ((size_t)bq * CC + d) * HWSZ + pq;
        stcs4(orow, o0);
        stcs4(orow + 4, o1);
    }
}

// ---------------------------------------------------------------------------
// launch
// ---------------------------------------------------------------------------
extern "C" void kernel_launch(void* const* d_in, const int* in_sizes, int n_in,
                              void* d_out, int out_size) {
    (void)in_sizes; (void)n_in; (void)out_size;
    const float* s      = (const float*)d_in[0];
    const float* r      = (const float*)d_in[1];
    const float* pw1    = (const float*)d_in[2];
    const float* pb1    = (const float*)d_in[3];
    const float* pw2    = (const float*)d_in[4];
    const float* pb2    = (const float*)d_in[5];
    const float* weight = (const float*)d_in[6];
    const float* bscale = (const float*)d_in[7];
    const float* pww    = (const float*)d_in[8];
    const float* pwb    = (const float*)d_in[9];
    float* out = (float*)d_out;

    pool_kernel<<<BB * CC, 256>>>(r);
    wgen_kernel<<<BB, 256>>>(pw1, pb1, pw2, pb2, weight, bscale);
    dw_kernel<<<BB * CC / 2, 256>>>(s);
    dim3 grid(NTOT / 128, CC / 128, 1);
    pw_gemm_kernel<<<grid, 256>>>(pww, pwb, out);
}

// round 7
// speedup vs baseline: 1.4252x; 1.2873x over previous
#include <cuda_runtime.h>
#include <cuda_bf16.h>
#include <cstdint>
#include <cstddef>

// Problem constants
#define BB   32
#define CC   256
#define HH   56
#define WW   56
#define HWSZ 3136          // 56*56
#define GG   4
#define KS   7
#define KK2  49            // 7*7
#define CRR  64            // C / 4
#define NTOT (BB * HWSZ)   // 100352 = 784 * 128

typedef unsigned long long ull;

// Scratch (device globals: allocation-free per harness rules)
__device__ float g_scratch[(size_t)BB * CC * HWSZ];   // gelu(dwconv(s))
__device__ float g_pooled[BB * CC];
__device__ float g_wk[(size_t)BB * CC * KK2];         // per-(b,c) 7x7 kernels
__device__ __nv_bfloat16 g_wb_hi[CC * CC];            // pw_w bf16 hi
__device__ __nv_bfloat16 g_wb_lo[CC * CC];            // pw_w bf16 lo

// ---------------------------------------------------------------------------
// generic helpers
// ---------------------------------------------------------------------------
__device__ __forceinline__ float gelu_f(float x) {
    return 0.5f * x * (1.0f + erff(x * 0.70710678118654752440f));
}
__device__ __forceinline__ ull pack2(float lo, float hi) {
    ull r; asm("mov.b64 %0, {%1, %2};" : "=l"(r) : "f"(lo), "f"(hi)); return r;
}
__device__ __forceinline__ void fma2(ull& d, ull a, ull b) {
    asm("fma.rn.f32x2 %0, %1, %2, %0;" : "+l"(d) : "l"(a), "l"(b));
}
__device__ __forceinline__ float2 unpack2(ull v) {
    float2 r; asm("mov.b64 {%0, %1}, %2;" : "=f"(r.x), "=f"(r.y) : "l"(v)); return r;
}
__device__ __forceinline__ float4 ldcs4(const float* p) {
    float4 v;
    asm("ld.global.cs.v4.f32 {%0,%1,%2,%3}, [%4];"
        : "=f"(v.x), "=f"(v.y), "=f"(v.z), "=f"(v.w) : "l"(p));
    return v;
}
__device__ __forceinline__ uint32_t pk_bf(__nv_bfloat16 a, __nv_bfloat16 b) {
    __nv_bfloat162 v(a, b);
    return *reinterpret_cast<uint32_t*>(&v);
}
__device__ __forceinline__ uint32_t smem_u32(const void* p) {
    uint32_t a;
    asm("{ .reg .u64 t; cvta.to.shared.u64 t, %1; cvt.u32.u64 %0, t; }"
        : "=r"(a) : "l"(p));
    return a;
}

// HMMA m16n8k16 bf16 (row.col), fp32 accumulate — portable sm_80+ path
__device__ __forceinline__ void hmma(float* c, const uint32_t* a, const uint32_t* b) {
    asm volatile(
        "mma.sync.aligned.m16n8k16.row.col.f32.bf16.bf16.f32 "
        "{%0,%1,%2,%3}, {%4,%5,%6,%7}, {%8,%9}, {%0,%1,%2,%3};"
        : "+f"(c[0]), "+f"(c[1]), "+f"(c[2]), "+f"(c[3])
        : "r"(a[0]), "r"(a[1]), "r"(a[2]), "r"(a[3]), "r"(b[0]), "r"(b[1]));
}
__device__ __forceinline__ void ldsm4(uint32_t* r, uint32_t addr) {
    asm volatile("ldmatrix.sync.aligned.m8n8.x4.shared.b16 {%0,%1,%2,%3}, [%4];"
                 : "=r"(r[0]), "=r"(r[1]), "=r"(r[2]), "=r"(r[3]) : "r"(addr));
}
__device__ __forceinline__ void ldsm4t(uint32_t* r, uint32_t addr) {
    asm volatile("ldmatrix.sync.aligned.m8n8.x4.trans.shared.b16 {%0,%1,%2,%3}, [%4];"
                 : "=r"(r[0]), "=r"(r[1]), "=r"(r[2]), "=r"(r[3]) : "r"(addr));
}

// ---------------------------------------------------------------------------
// Kernel 1: pooled[b,c] = mean over H,W of r  (unchanged)
// ---------------------------------------------------------------------------
__global__ void pool_kernel(const float* __restrict__ r) {
    const int bc = blockIdx.x;
    const float* p = r + (size_t)bc * HWSZ;
    float s = 0.f;
    #pragma unroll 4
    for (int i = threadIdx.x; i < HWSZ / 4; i += 256) {
        float4 v = ldcs4(p + i * 4);
        s += (v.x + v.y) + (v.z + v.w);
    }
    __shared__ float red[8];
    #pragma unroll
    for (int o = 16; o > 0; o >>= 1) s += __shfl_down_sync(0xFFFFFFFFu, s, o);
    if ((threadIdx.x & 31) == 0) red[threadIdx.x >> 5] = s;
    __syncthreads();
    if (threadIdx.x < 8) {
        s = red[threadIdx.x];
        #pragma unroll
        for (int o = 4; o > 0; o >>= 1) s += __shfl_down_sync(0xFFu, s, o);
        if (threadIdx.x == 0) g_pooled[bc] = s * (1.0f / (float)HWSZ);
    }
}

// ---------------------------------------------------------------------------
// Kernel 2: SE weight generation -> g_wk[b,c,49]  (unchanged)
// ---------------------------------------------------------------------------
__global__ void wgen_kernel(const float* __restrict__ w1, const float* __restrict__ b1,
                            const float* __restrict__ w2, const float* __restrict__ b2,
                            const float* __restrict__ weight, const float* __restrict__ bscale) {
    const int b = blockIdx.x;
    const int t = threadIdx.x;
    __shared__ float ps[CC];
    __shared__ float hs[CRR];

    ps[t] = g_pooled[b * CC + t];
    __syncthreads();

    if (t < CRR) {
        float acc = b1[t];
        const float* wr = w1 + (size_t)t * CC;
        #pragma unroll 4
        for (int c = 0; c < CC; c++) acc = fmaf(ps[c], wr[c], acc);
        hs[t] = gelu_f(acc);
    }
    __syncthreads();

    float vals[GG][2];
    #pragma unroll
    for (int g = 0; g < GG; g++) {
        #pragma unroll
        for (int e = 0; e < 2; e++) {
            const int row = (g * CC + t) * 2 + e;
            float acc = b2[row];
            const float* wr = w2 + (size_t)row * CRR;
            #pragma unroll 4
            for (int k = 0; k < CRR; k++) acc = fmaf(hs[k], wr[k], acc);
            vals[g][e] = acc;
        }
    }

    float m = fmaxf(fmaxf(vals[0][0], vals[1][0]), fmaxf(vals[2][0], vals[3][0]));
    float alpha[GG];
    float ssum = 0.f;
    #pragma unroll
    for (int g = 0; g < GG; g++) { alpha[g] = expf(vals[g][0] - m); ssum += alpha[g]; }
    const float inv = 1.0f / ssum;
    float betasum = 0.f;
    #pragma unroll
    for (int g = 0; g < GG; g++) {
        alpha[g] *= inv;
        betasum += tanhf(vals[g][1] * expf(bscale[g * CC + t]) * 0.1f);
    }

    float* out = g_wk + ((size_t)b * CC + t) * KK2;
    #pragma unroll
    for (int k = 0; k < KK2; k++) {
        float acc = betasum;
        #pragma unroll
        for (int g = 0; g < GG; g++)
            acc = fmaf(alpha[g], weight[((size_t)g * CC + t) * KK2 + k], acc);
        out[k] = acc;
    }
}

// ---------------------------------------------------------------------------
// Kernel 2b: preconvert pw_w -> bf16 hi/lo  (65536 elements)
// ---------------------------------------------------------------------------
__global__ void wconv_kernel(const float* __restrict__ w) {
    const int i = blockIdx.x * 256 + threadIdx.x;
    const float x = w[i];
    const __nv_bfloat16 h = __float2bfloat16(x);
    g_wb_hi[i] = h;
    g_wb_lo[i] = __float2bfloat16(x - __bfloat162float(h));
}

// ---------------------------------------------------------------------------
// Kernel 3: dynamic depthwise 7x7 conv (pad 3) + exact GELU -> g_scratch
// (unchanged from R5)
// ---------------------------------------------------------------------------
__global__ void __launch_bounds__(256, 2) dw_kernel(const float* __restrict__ s) {
    const int bc0 = blockIdx.x * 2;
    __shared__ __align__(16) float sm[2][62 * 64];
    __shared__ ull wsm[2][KK2];
    const int t = threadIdx.x;

    if (t < 2 * KK2) {
        const int pl = t / KK2;
        const int k = t - pl * KK2;
        const float w = g_wk[(size_t)(bc0 + pl) * KK2 + k];
        wsm[pl][k] = pack2(w, w);
    }

    for (int i = t; i < 2 * 62 * 64; i += 256) {
        const int pl = i / (62 * 64);
        const int j = i - pl * (62 * 64);
        const int yy = j >> 6, xx = j & 63;
        const int y = yy - 3, x = xx - 3;
        float v = 0.f;
        if ((unsigned)y < 56u && (unsigned)x < 56u)
            v = __ldcs(s + (size_t)(bc0 + pl) * HWSZ + y * WW + x);
        sm[pl][yy * 64 + xx] = v;
    }
    __syncthreads();

    if (t >= 196) return;
    const int pl = t / 98;
    const int v = t - pl * 98;
    const int ytile = v / 7;
    const int xtile = v - ytile * 7;
    const int y0 = ytile * 4;
    const int x0 = xtile * 8;
    const float* __restrict__ smp = sm[pl];
    const ull* __restrict__ wp = wsm[pl];
    float* __restrict__ out = g_scratch + (size_t)(bc0 + pl) * HWSZ;

    ull acc[4][4];
    #pragma unroll
    for (int oy = 0; oy < 4; oy++)
        #pragma unroll
        for (int j = 0; j < 4; j++) acc[oy][j] = 0ull;

    #pragma unroll
    for (int r = 0; r < 10; r++) {
        const float* row = &smp[(y0 + r) * 64 + x0];
        const float4 q0 = *reinterpret_cast<const float4*>(row);
        const float4 q1 = *reinterpret_cast<const float4*>(row + 4);
        const float4 q2 = *reinterpret_cast<const float4*>(row + 8);
        const float4 q3 = *reinterpret_cast<const float4*>(row + 12);
        const float f[16] = {q0.x, q0.y, q0.z, q0.w, q1.x, q1.y, q1.z, q1.w,
                             q2.x, q2.y, q2.z, q2.w, q3.x, q3.y, q3.z, q3.w};
        ull p[13];
        #pragma unroll
        for (int i = 0; i < 13; i++) p[i] = pack2(f[i], f[i + 1]);

        #pragma unroll
        for (int oy = 0; oy < 4; oy++) {
            const int ky = r - oy;
            if (ky >= 0 && ky < 7) {
                #pragma unroll
                for (int kx = 0; kx < 7; kx++) {
                    const ull w = wp[ky * 7 + kx];
                    fma2(acc[oy][0], w, p[kx]);
                    fma2(acc[oy][1], w, p[kx + 2]);
                    fma2(acc[oy][2], w, p[kx + 4]);
                    fma2(acc[oy][3], w, p[kx + 6]);
                }
            }
        }
    }

    #pragma unroll
    for (int oy = 0; oy < 4; oy++) {
        const float2 v0 = unpack2(acc[oy][0]);
        const float2 v1 = unpack2(acc[oy][1]);
        const float2 v2 = unpack2(acc[oy][2]);
        const float2 v3 = unpack2(acc[oy][3]);
        float4 o0, o1;
        o0.x = gelu_f(v0.x); o0.y = gelu_f(v0.y); o0.z = gelu_f(v1.x); o0.w = gelu_f(v1.y);
        o1.x = gelu_f(v2.x); o1.y = gelu_f(v2.y); o1.z = gelu_f(v3.x); o1.w = gelu_f(v3.y);
        float* orow = out + (y0 + oy) * WW + x0;
        *reinterpret_cast<float4*>(orow) = o0;
        *reinterpret_cast<float4*>(orow + 4) = o1;
    }
}

// ---------------------------------------------------------------------------
// Kernel 4: pointwise conv on tensor cores via mma.sync bf16 (3-term split)
//
//   C[d][n] = sum_c W[d][c] * S[c][n],  W split hi/lo (precomputed),
//   S split hi/lo at STS time.  D = Wh*Sh + Wh*Sl + Wl*Sh.
//
// Block: 256 thr (8 warps), tile 128(d) x 128(n), K-chunk 32, single-buffer.
// Warp tile 64x32 = 4 m-frags x 4 n-frags (m16n8k16).
// A smem: [128][k32] bf16, row stride 40 bf16 (80B -> LDSM conflict-free)
// B smem: [k32][128] bf16, row stride 136 bf16 (272B -> conflict-free),
//         loaded via ldmatrix.x4.trans.
// grid = (784, 2).
// ---------------------------------------------------------------------------
#define A_STRIDE 40     // bf16 elems per A smem row (80 B)
#define B_STRIDE 136    // bf16 elems per B smem row (272 B)

__global__ void __launch_bounds__(256, 1) pw_mma_kernel(const float* __restrict__ bias,
                                                        float* __restrict__ out) {
    __shared__ __align__(16) __nv_bfloat16 Ah[128 * A_STRIDE];
    __shared__ __align__(16) __nv_bfloat16 Al[128 * A_STRIDE];
    __shared__ __align__(16) __nv_bfloat16 Bh[32 * B_STRIDE];
    __shared__ __align__(16) __nv_bfloat16 Bl[32 * B_STRIDE];
    __shared__ float sbias[128];

    const int t = threadIdx.x;
    const int lane = t & 31;
    const int wid = t >> 5;
    const int n0 = blockIdx.x * 128;
    const int dBase = blockIdx.y * 128;

    const int m_warp = (wid >> 2) * 64;   // 0 or 64
    const int n_warp = (wid & 3) * 32;    // 0..96

    if (t < 128) sbias[t] = bias[dBase + t];

    // ---- global load assignments ----
    // A: thread t -> row d = t>>1, k-half = (t&1)*16  (16 bf16 = 2 uint4)
    const int a_d = t >> 1;
    const int a_k = (t & 1) * 16;
    const size_t a_gidx = (size_t)(dBase + a_d) * CC + a_k;
    // B: thread t -> k row = t>>3, 16 n at (t&7)*16
    const int b_k = t >> 3;
    const int b_n = (t & 7) * 16;
    const int n_t = n0 + b_n;                 // 16-aligned, 16 | 3136 -> one batch
    const int b_bt = n_t / HWSZ;
    const float* __restrict__ Bg =
        g_scratch + ((size_t)b_bt * CC + b_k) * HWSZ + (n_t - b_bt * HWSZ);

    // staged regs
    uint4 sAh0, sAh1, sAl0, sAl1;
    uint32_t sBh[8], sBl[8];

    auto load_global = [&](int ch) {
        const int c0 = ch * 32;
        const __nv_bfloat16* ph = g_wb_hi + a_gidx + c0;
        const __nv_bfloat16* pl = g_wb_lo + a_gidx + c0;
        sAh0 = *reinterpret_cast<const uint4*>(ph);
        sAh1 = *reinterpret_cast<const uint4*>(ph + 8);
        sAl0 = *reinterpret_cast<const uint4*>(pl);
        sAl1 = *reinterpret_cast<const uint4*>(pl + 8);
        const float* pb = Bg + (size_t)c0 * HWSZ;
        #pragma unroll
        for (int q = 0; q < 4; q++) {
            const float4 f = *reinterpret_cast<const float4*>(pb + q * 4);
            const __nv_bfloat16 h0 = __float2bfloat16(f.x);
            const __nv_bfloat16 h1 = __float2bfloat16(f.y);
            const __nv_bfloat16 h2 = __float2bfloat16(f.z);
            const __nv_bfloat16 h3 = __float2bfloat16(f.w);
            sBh[q * 2 + 0] = pk_bf(h0, h1);
            sBh[q * 2 + 1] = pk_bf(h2, h3);
            sBl[q * 2 + 0] = pk_bf(__float2bfloat16(f.x - __bfloat162float(h0)),
                                   __float2bfloat16(f.y - __bfloat162float(h1)));
            sBl[q * 2 + 1] = pk_bf(__float2bfloat16(f.z - __bfloat162float(h2)),
                                   __float2bfloat16(f.w - __bfloat162float(h3)));
        }
    };

    auto sts_stage = [&]() {
        __nv_bfloat16* pah = Ah + a_d * A_STRIDE + a_k;
        __nv_bfloat16* pal = Al + a_d * A_STRIDE + a_k;
        *reinterpret_cast<uint4*>(pah) = sAh0;
        *reinterpret_cast<uint4*>(pah + 8) = sAh1;
        *reinterpret_cast<uint4*>(pal) = sAl0;
        *reinterpret_cast<uint4*>(pal + 8) = sAl1;
        __nv_bfloat16* pbh = Bh + b_k * B_STRIDE + b_n;
        __nv_bfloat16* pbl = Bl + b_k * B_STRIDE + b_n;
        *reinterpret_cast<uint4*>(pbh) = make_uint4(sBh[0], sBh[1], sBh[2], sBh[3]);
        *reinterpret_cast<uint4*>(pbh + 8) = make_uint4(sBh[4], sBh[5], sBh[6], sBh[7]);
        *reinterpret_cast<uint4*>(pbl) = make_uint4(sBl[0], sBl[1], sBl[2], sBl[3]);
        *reinterpret_cast<uint4*>(pbl + 8) = make_uint4(sBl[4], sBl[5], sBl[6], sBl[7]);
    };

    // ---- LDSM lane addressing (bytes) ----
    // A (non-trans x4): row = m_warp + (lane&7) + ((lane>>3)&1)*8, kchunk = lane>>4
    const int a_row = m_warp + (lane & 7) + ((lane >> 3) & 1) * 8;
    const uint32_t aAh = smem_u32(Ah) + a_row * (A_STRIDE * 2) + (lane >> 4) * 16;
    const uint32_t aAl = smem_u32(Al) + a_row * (A_STRIDE * 2) + (lane >> 4) * 16;
    // B (trans x4): k = ((lane>>3)&1)*8 + (lane&7), ncol = n_warp + (lane>>4)*8
    const int b_krow = ((lane >> 3) & 1) * 8 + (lane & 7);
    const int b_ncol = n_warp + (lane >> 4) * 8;
    const uint32_t aBh = smem_u32(Bh) + b_krow * (B_STRIDE * 2) + b_ncol * 2;
    const uint32_t aBl = smem_u32(Bl) + b_krow * (B_STRIDE * 2) + b_ncol * 2;

    float acc[4][4][4];
    #pragma unroll
    for (int i = 0; i < 4; i++)
        #pragma unroll
        for (int j = 0; j < 4; j++)
            #pragma unroll
            for (int q = 0; q < 4; q++) acc[i][j][q] = 0.f;

    load_global(0);
    for (int ch = 0; ch < 8; ch++) {
        if (ch) __syncthreads();
        sts_stage();
        __syncthreads();
        if (ch < 7) load_global(ch + 1);

        #pragma unroll
        for (int ks = 0; ks < 2; ks++) {
            // B fragments: 2 x4.trans per matrix (hi & lo) cover 4 n-frags
            uint32_t bh[4][2], bl[4][2];
            #pragma unroll
            for (int nfp = 0; nfp < 2; nfp++) {
                uint32_t r[4];
                ldsm4t(r, aBh + ks * 16 * (B_STRIDE * 2) + nfp * 32);
                bh[nfp * 2 + 0][0] = r[0]; bh[nfp * 2 + 0][1] = r[1];
                bh[nfp * 2 + 1][0] = r[2]; bh[nfp * 2 + 1][1] = r[3];
                ldsm4t(r, aBl + ks * 16 * (B_STRIDE * 2) + nfp * 32);
                bl[nfp * 2 + 0][0] = r[0]; bl[nfp * 2 + 0][1] = r[1];
                bl[nfp * 2 + 1][0] = r[2]; bl[nfp * 2 + 1][1] = r[3];
            }
            #pragma unroll
            for (int mf = 0; mf < 4; mf++) {
                uint32_t ah[4], al[4];
                ldsm4(ah, aAh + mf * 16 * (A_STRIDE * 2) + ks * 32);
                ldsm4(al, aAl + mf * 16 * (A_STRIDE * 2) + ks * 32);
                #pragma unroll
                for (int nf = 0; nf < 4; nf++) {
                    hmma(acc[mf][nf], ah, bh[nf]);
                    hmma(acc[mf][nf], ah, bl[nf]);
                    hmma(acc[mf][nf], al, bh[nf]);
                }
            }
        }
    }

    // ---- epilogue ----
    const int g = lane >> 2;
    const int tig = lane & 3;
    #pragma unroll
    for (int nf = 0; nf < 4; nf++) {
        const int nt = n0 + n_warp + nf * 8 + tig * 2;
        const int bt = nt / HWSZ;
        const int pp = nt - bt * HWSZ;
        #pragma unroll
        for (int mf = 0; mf < 4; mf++) {
            const int d0 = dBase + m_warp + mf * 16 + g;
            const float bb0 = sbias[d0 - dBase];
            const float bb1 = sbias[d0 - dBase + 8];
            float2 v0, v1;
            v0.x = acc[mf][nf][0] + bb0;
            v0.y = acc[mf][nf][1] + bb0;
            v1.x = acc[mf][nf][2] + bb1;
            v1.y = acc[mf][nf][3] + bb1;
            *reinterpret_cast<float2*>(out + ((size_t)bt * CC + d0) * HWSZ + pp) = v0;
            *reinterpret_cast<float2*>(out + ((size_t)bt * CC + d0 + 8) * HWSZ + pp) = v1;
        }
    }
}

// ---------------------------------------------------------------------------
// launch
// ---------------------------------------------------------------------------
extern "C" void kernel_launch(void* const* d_in, const int* in_sizes, int n_in,
                              void* d_out, int out_size) {
    (void)in_sizes; (void)n_in; (void)out_size;
    const float* s      = (const float*)d_in[0];
    const float* r      = (const float*)d_in[1];
    const float* pw1    = (const float*)d_in[2];
    const float* pb1    = (const float*)d_in[3];
    const float* pw2    = (const float*)d_in[4];
    const float* pb2    = (const float*)d_in[5];
    const float* weight = (const float*)d_in[6];
    const float* bscale = (const float*)d_in[7];
    const float* pww    = (const float*)d_in[8];
    const float* pwb    = (const float*)d_in[9];
    float* out = (float*)d_out;

    pool_kernel<<<BB * CC, 256>>>(r);
    wgen_kernel<<<BB, 256>>>(pw1, pb1, pw2, pb2, weight, bscale);
    wconv_kernel<<<CC * CC / 256, 256>>>(pww);
    dw_kernel<<<BB * CC / 2, 256>>>(s);
    dim3 grid(NTOT / 128, CC / 128, 1);
    pw_mma_kernel<<<grid, 256>>>(pwb, out);
}

// round 8
// speedup vs baseline: 1.7385x; 1.2199x over previous
#include <cuda_runtime.h>
#include <cuda_bf16.h>
#include <cstdint>
#include <cstddef>

// Problem constants
#define BB   32
#define CC   256
#define HH   56
#define WW   56
#define HWSZ 3136          // 56*56
#define GG   4
#define KS   7
#define KK2  49            // 7*7
#define CRR  64            // C / 4
#define NTOT (BB * HWSZ)   // 100352 = 784 * 128

typedef unsigned long long ull;

// Scratch (device globals: allocation-free per harness rules)
__device__ __nv_bfloat16 g_sc_hi[(size_t)BB * CC * HWSZ];  // gelu(dw) bf16 hi
__device__ __nv_bfloat16 g_sc_lo[(size_t)BB * CC * HWSZ];  // gelu(dw) bf16 lo
__device__ float g_pooled[BB * CC];
__device__ float g_wk[(size_t)BB * CC * KK2];              // per-(b,c) 7x7 kernels
__device__ __nv_bfloat16 g_wb_hi[CC * CC];                 // pw_w bf16 hi
__device__ __nv_bfloat16 g_wb_lo[CC * CC];                 // pw_w bf16 lo

// ---------------------------------------------------------------------------
// generic helpers
// ---------------------------------------------------------------------------
__device__ __forceinline__ float gelu_f(float x) {
    return 0.5f * x * (1.0f + erff(x * 0.70710678118654752440f));
}
__device__ __forceinline__ ull pack2(float lo, float hi) {
    ull r; asm("mov.b64 %0, {%1, %2};" : "=l"(r) : "f"(lo), "f"(hi)); return r;
}
__device__ __forceinline__ void fma2(ull& d, ull a, ull b) {
    asm("fma.rn.f32x2 %0, %1, %2, %0;" : "+l"(d) : "l"(a), "l"(b));
}
__device__ __forceinline__ float2 unpack2(ull v) {
    float2 r; asm("mov.b64 {%0, %1}, %2;" : "=f"(r.x), "=f"(r.y) : "l"(v)); return r;
}
__device__ __forceinline__ float4 ldcs4(const float* p) {
    float4 v;
    asm("ld.global.cs.v4.f32 {%0,%1,%2,%3}, [%4];"
        : "=f"(v.x), "=f"(v.y), "=f"(v.z), "=f"(v.w) : "l"(p));
    return v;
}
__device__ __forceinline__ void stcs2(float* p, float2 v) {
    asm("st.global.cs.v2.f32 [%0], {%1,%2};" :: "l"(p), "f"(v.x), "f"(v.y));
}
__device__ __forceinline__ uint32_t pk_bf(__nv_bfloat16 a, __nv_bfloat16 b) {
    __nv_bfloat162 v(a, b);
    return *reinterpret_cast<uint32_t*>(&v);
}
__device__ __forceinline__ uint32_t smem_u32(const void* p) {
    uint32_t a;
    asm("{ .reg .u64 t; cvta.to.shared.u64 t, %1; cvt.u32.u64 %0, t; }"
        : "=r"(a) : "l"(p));
    return a;
}
__device__ __forceinline__ void cpa16(uint32_t dst, const void* src) {
    asm volatile("cp.async.cg.shared.global [%0], [%1], 16;" :: "r"(dst), "l"(src));
}
#define CPA_COMMIT() asm volatile("cp.async.commit_group;" ::: "memory")
#define CPA_WAIT0()  asm volatile("cp.async.wait_group 0;" ::: "memory")

// HMMA m16n8k16 bf16 (row.col), fp32 accumulate — portable sm_80+ path
__device__ __forceinline__ void hmma(float* c, const uint32_t* a, const uint32_t* b) {
    asm volatile(
        "mma.sync.aligned.m16n8k16.row.col.f32.bf16.bf16.f32 "
        "{%0,%1,%2,%3}, {%4,%5,%6,%7}, {%8,%9}, {%0,%1,%2,%3};"
        : "+f"(c[0]), "+f"(c[1]), "+f"(c[2]), "+f"(c[3])
        : "r"(a[0]), "r"(a[1]), "r"(a[2]), "r"(a[3]), "r"(b[0]), "r"(b[1]));
}
__device__ __forceinline__ void ldsm4(uint32_t* r, uint32_t addr) {
    asm volatile("ldmatrix.sync.aligned.m8n8.x4.shared.b16 {%0,%1,%2,%3}, [%4];"
                 : "=r"(r[0]), "=r"(r[1]), "=r"(r[2]), "=r"(r[3]) : "r"(addr));
}
__device__ __forceinline__ void ldsm4t(uint32_t* r, uint32_t addr) {
    asm volatile("ldmatrix.sync.aligned.m8n8.x4.trans.shared.b16 {%0,%1,%2,%3}, [%4];"
                 : "=r"(r[0]), "=r"(r[1]), "=r"(r[2]), "=r"(r[3]) : "r"(addr));
}

// ---------------------------------------------------------------------------
// Kernel 1: pooled[b,c] = mean over H,W of r
// ---------------------------------------------------------------------------
__global__ void pool_kernel(const float* __restrict__ r) {
    const int bc = blockIdx.x;
    const float* p = r + (size_t)bc * HWSZ;
    float s = 0.f;
    #pragma unroll 4
    for (int i = threadIdx.x; i < HWSZ / 4; i += 256) {
        float4 v = ldcs4(p + i * 4);
        s += (v.x + v.y) + (v.z + v.w);
    }
    __shared__ float red[8];
    #pragma unroll
    for (int o = 16; o > 0; o >>= 1) s += __shfl_down_sync(0xFFFFFFFFu, s, o);
    if ((threadIdx.x & 31) == 0) red[threadIdx.x >> 5] = s;
    __syncthreads();
    if (threadIdx.x < 8) {
        s = red[threadIdx.x];
        #pragma unroll
        for (int o = 4; o > 0; o >>= 1) s += __shfl_down_sync(0xFFu, s, o);
        if (threadIdx.x == 0) g_pooled[bc] = s * (1.0f / (float)HWSZ);
    }
}

// ---------------------------------------------------------------------------
// Kernel 2: SE weight generation -> g_wk[b,c,49]
// ---------------------------------------------------------------------------
__global__ void wgen_kernel(const float* __restrict__ w1, const float* __restrict__ b1,
                            const float* __restrict__ w2, const float* __restrict__ b2,
                            const float* __restrict__ weight, const float* __restrict__ bscale) {
    const int b = blockIdx.x;
    const int t = threadIdx.x;
    __shared__ float ps[CC];
    __shared__ float hs[CRR];

    ps[t] = g_pooled[b * CC + t];
    __syncthreads();

    if (t < CRR) {
        float acc = b1[t];
        const float* wr = w1 + (size_t)t * CC;
        #pragma unroll 4
        for (int c = 0; c < CC; c++) acc = fmaf(ps[c], wr[c], acc);
        hs[t] = gelu_f(acc);
    }
    __syncthreads();

    float vals[GG][2];
    #pragma unroll
    for (int g = 0; g < GG; g++) {
        #pragma unroll
        for (int e = 0; e < 2; e++) {
            const int row = (g * CC + t) * 2 + e;
            float acc = b2[row];
            const float* wr = w2 + (size_t)row * CRR;
            #pragma unroll 4
            for (int k = 0; k < CRR; k++) acc = fmaf(hs[k], wr[k], acc);
            vals[g][e] = acc;
        }
    }

    float m = fmaxf(fmaxf(vals[0][0], vals[1][0]), fmaxf(vals[2][0], vals[3][0]));
    float alpha[GG];
    float ssum = 0.f;
    #pragma unroll
    for (int g = 0; g < GG; g++) { alpha[g] = expf(vals[g][0] - m); ssum += alpha[g]; }
    const float inv = 1.0f / ssum;
    float betasum = 0.f;
    #pragma unroll
    for (int g = 0; g < GG; g++) {
        alpha[g] *= inv;
        betasum += tanhf(vals[g][1] * expf(bscale[g * CC + t]) * 0.1f);
    }

    float* out = g_wk + ((size_t)b * CC + t) * KK2;
    #pragma unroll
    for (int k = 0; k < KK2; k++) {
        float acc = betasum;
        #pragma unroll
        for (int g = 0; g < GG; g++)
            acc = fmaf(alpha[g], weight[((size_t)g * CC + t) * KK2 + k], acc);
        out[k] = acc;
    }
}

// ---------------------------------------------------------------------------
// Kernel 2b: preconvert pw_w -> bf16 hi/lo  (65536 elements)
// ---------------------------------------------------------------------------
__global__ void wconv_kernel(const float* __restrict__ w) {
    const int i = blockIdx.x * 256 + threadIdx.x;
    const float x = w[i];
    const __nv_bfloat16 h = __float2bfloat16(x);
    g_wb_hi[i] = h;
    g_wb_lo[i] = __float2bfloat16(x - __bfloat162float(h));
}

// ---------------------------------------------------------------------------
// Kernel 3: dynamic depthwise 7x7 conv (pad 3) + exact GELU -> bf16 hi/lo
// 2 planes per 256-thread block. Vectorized load phase: zero-fill smem,
// then float4 interior loads (no per-element bounds checks).
// Per-thread 4x8 tile, packed f32x2 FMA; epilogue splits to bf16 hi/lo.
// ---------------------------------------------------------------------------
__global__ void __launch_bounds__(256, 2) dw_kernel(const float* __restrict__ s) {
    const int bc0 = blockIdx.x * 2;
    __shared__ __align__(16) float sm[2][62 * 64];
    __shared__ ull wsm[2][KK2];
    const int t = threadIdx.x;

    // zero-fill both padded planes (vectorized)
    {
        float4* z = reinterpret_cast<float4*>(&sm[0][0]);
        const float4 zv = make_float4(0.f, 0.f, 0.f, 0.f);
        #pragma unroll
        for (int i = t; i < 2 * 62 * 64 / 4; i += 256) z[i] = zv;
    }
    // weight prepack
    if (t < 2 * KK2) {
        const int pl = t / KK2;
        const int k = t - pl * KK2;
        const float w = g_wk[(size_t)(bc0 + pl) * KK2 + k];
        wsm[pl][k] = pack2(w, w);
    }
    __syncthreads();

    // interior load: 56 rows x 14 float4 per plane (784 per plane)
    for (int i = t; i < 2 * 784; i += 256) {
        const int pl = (i >= 784) ? 1 : 0;
        const int j = i - pl * 784;
        const int y = j / 14;
        const int x4 = j - y * 14;
        const float4 v = ldcs4(s + (size_t)(bc0 + pl) * HWSZ + y * WW + x4 * 4);
        float* dst = &sm[pl][(y + 3) * 64 + 3 + x4 * 4];
        dst[0] = v.x; dst[1] = v.y; dst[2] = v.z; dst[3] = v.w;
    }
    __syncthreads();

    if (t >= 196) return;
    const int pl = t / 98;
    const int v = t - pl * 98;
    const int ytile = v / 7;
    const int xtile = v - ytile * 7;
    const int y0 = ytile * 4;
    const int x0 = xtile * 8;
    const float* __restrict__ smp = sm[pl];
    const ull* __restrict__ wp = wsm[pl];
    const size_t obase = (size_t)(bc0 + pl) * HWSZ;

    ull acc[4][4];
    #pragma unroll
    for (int oy = 0; oy < 4; oy++)
        #pragma unroll
        for (int j = 0; j < 4; j++) acc[oy][j] = 0ull;

    #pragma unroll
    for (int r = 0; r < 10; r++) {
        const float* row = &smp[(y0 + r) * 64 + x0];
        const float4 q0 = *reinterpret_cast<const float4*>(row);
        const float4 q1 = *reinterpret_cast<const float4*>(row + 4);
        const float4 q2 = *reinterpret_cast<const float4*>(row + 8);
        const float4 q3 = *reinterpret_cast<const float4*>(row + 12);
        const float f[16] = {q0.x, q0.y, q0.z, q0.w, q1.x, q1.y, q1.z, q1.w,
                             q2.x, q2.y, q2.z, q2.w, q3.x, q3.y, q3.z, q3.w};
        ull p[13];
        #pragma unroll
        for (int i = 0; i < 13; i++) p[i] = pack2(f[i], f[i + 1]);

        #pragma unroll
        for (int oy = 0; oy < 4; oy++) {
            const int ky = r - oy;
            if (ky >= 0 && ky < 7) {
                #pragma unroll
                for (int kx = 0; kx < 7; kx++) {
                    const ull w = wp[ky * 7 + kx];
                    fma2(acc[oy][0], w, p[kx]);
                    fma2(acc[oy][1], w, p[kx + 2]);
                    fma2(acc[oy][2], w, p[kx + 4]);
                    fma2(acc[oy][3], w, p[kx + 6]);
                }
            }
        }
    }

    #pragma unroll
    for (int oy = 0; oy < 4; oy++) {
        const float2 v0 = unpack2(acc[oy][0]);
        const float2 v1 = unpack2(acc[oy][1]);
        const float2 v2 = unpack2(acc[oy][2]);
        const float2 v3 = unpack2(acc[oy][3]);
        float g[8];
        g[0] = gelu_f(v0.x); g[1] = gelu_f(v0.y); g[2] = gelu_f(v1.x); g[3] = gelu_f(v1.y);
        g[4] = gelu_f(v2.x); g[5] = gelu_f(v2.y); g[6] = gelu_f(v3.x); g[7] = gelu_f(v3.y);
        uint32_t hw[4], lw[4];
        #pragma unroll
        for (int q = 0; q < 4; q++) {
            const __nv_bfloat16 h0 = __float2bfloat16(g[2 * q]);
            const __nv_bfloat16 h1 = __float2bfloat16(g[2 * q + 1]);
            hw[q] = pk_bf(h0, h1);
            lw[q] = pk_bf(__float2bfloat16(g[2 * q] - __bfloat162float(h0)),
                          __float2bfloat16(g[2 * q + 1] - __bfloat162float(h1)));
        }
        const size_t off = obase + (y0 + oy) * WW + x0;
        *reinterpret_cast<uint4*>(g_sc_hi + off) = make_uint4(hw[0], hw[1], hw[2], hw[3]);
        *reinterpret_cast<uint4*>(g_sc_lo + off) = make_uint4(lw[0], lw[1], lw[2], lw[3]);
    }
}

// ---------------------------------------------------------------------------
// Kernel 4: pointwise conv on tensor cores (mma.sync bf16, 3-term split)
// cp.async loads (no staging regs) -> 2 blocks/SM for cross-block overlap.
// Tile 128(d) x 128(n), K-chunk 32, warp tile 64x32.
// ---------------------------------------------------------------------------
#define A_STRIDE 40     // bf16 elems per A smem row (80 B)
#define B_STRIDE 136    // bf16 elems per B smem row (272 B)

__global__ void __launch_bounds__(256, 2) pw_mma_kernel(const float* __restrict__ bias,
                                                        float* __restrict__ out) {
    __shared__ __align__(16) __nv_bfloat16 Ah[128 * A_STRIDE];
    __shared__ __align__(16) __nv_bfloat16 Al[128 * A_STRIDE];
    __shared__ __align__(16) __nv_bfloat16 Bh[32 * B_STRIDE];
    __shared__ __align__(16) __nv_bfloat16 Bl[32 * B_STRIDE];
    __shared__ float sbias[128];

    const int t = threadIdx.x;
    const int lane = t & 31;
    const int wid = t >> 5;
    const int n0 = blockIdx.x * 128;
    const int dBase = blockIdx.y * 128;

    const int m_warp = (wid >> 2) * 64;   // 0 or 64
    const int n_warp = (wid & 3) * 32;    // 0..96

    if (t < 128) sbias[t] = bias[dBase + t];

    // ---- cp.async assignments ----
    // A: thread t -> row d = t>>1, k-half = (t&1)*16 (32 B = 2 cp.16)
    const int a_d = t >> 1;
    const int a_k = (t & 1) * 16;
    const size_t a_gidx = (size_t)(dBase + a_d) * CC + a_k;
    const uint32_t dAh = smem_u32(Ah) + (a_d * A_STRIDE + a_k) * 2;
    const uint32_t dAl = smem_u32(Al) + (a_d * A_STRIDE + a_k) * 2;
    // B: thread t -> k row = t>>3 (0..31), 16 n at (t&7)*16
    const int b_k = t >> 3;
    const int b_n = (t & 7) * 16;
    const int n_t = n0 + b_n;                 // 16 | 3136 -> single batch
    const int b_bt = n_t / HWSZ;
    const size_t b_gbase = ((size_t)b_bt * CC + b_k) * HWSZ + (n_t - b_bt * HWSZ);
    const uint32_t dBh = smem_u32(Bh) + (b_k * B_STRIDE + b_n) * 2;
    const uint32_t dBl = smem_u32(Bl) + (b_k * B_STRIDE + b_n) * 2;

    // ---- LDSM lane addressing ----
    const int a_row = m_warp + (lane & 7) + ((lane >> 3) & 1) * 8;
    const uint32_t aAh = smem_u32(Ah) + a_row * (A_STRIDE * 2) + (lane >> 4) * 16;
    const uint32_t aAl = smem_u32(Al) + a_row * (A_STRIDE * 2) + (lane >> 4) * 16;
    const int b_krow = ((lane >> 3) & 1) * 8 + (lane & 7);
    const int b_ncol = n_warp + (lane >> 4) * 8;
    const uint32_t aBh = smem_u32(Bh) + b_krow * (B_STRIDE * 2) + b_ncol * 2;
    const uint32_t aBl = smem_u32(Bl) + b_krow * (B_STRIDE * 2) + b_ncol * 2;

    float acc[4][4][4];
    #pragma unroll
    for (int i = 0; i < 4; i++)
        #pragma unroll
        for (int j = 0; j < 4; j++)
            #pragma unroll
            for (int q = 0; q < 4; q++) acc[i][j][q] = 0.f;

    for (int ch = 0; ch < 8; ch++) {
        const int c0 = ch * 32;
        // issue async loads for this chunk
        cpa16(dAh,      g_wb_hi + a_gidx + c0);
        cpa16(dAh + 16, g_wb_hi + a_gidx + c0 + 8);
        cpa16(dAl,      g_wb_lo + a_gidx + c0);
        cpa16(dAl + 16, g_wb_lo + a_gidx + c0 + 8);
        const size_t bg = b_gbase + (size_t)c0 * HWSZ;
        cpa16(dBh,      g_sc_hi + bg);
        cpa16(dBh + 16, g_sc_hi + bg + 8);
        cpa16(dBl,      g_sc_lo + bg);
        cpa16(dBl + 16, g_sc_lo + bg + 8);
        CPA_COMMIT();
        CPA_WAIT0();
        __syncthreads();

        #pragma unroll
        for (int ks = 0; ks < 2; ks++) {
            uint32_t bh[4][2], bl[4][2];
            #pragma unroll
            for (int nfp = 0; nfp < 2; nfp++) {
                uint32_t r[4];
                ldsm4t(r, aBh + ks * 16 * (B_STRIDE * 2) + nfp * 32);
                bh[nfp * 2 + 0][0] = r[0]; bh[nfp * 2 + 0][1] = r[1];
                bh[nfp * 2 + 1][0] = r[2]; bh[nfp * 2 + 1][1] = r[3];
                ldsm4t(r, aBl + ks * 16 * (B_STRIDE * 2) + nfp * 32);
                bl[nfp * 2 + 0][0] = r[0]; bl[nfp * 2 + 0][1] = r[1];
                bl[nfp * 2 + 1][0] = r[2]; bl[nfp * 2 + 1][1] = r[3];
            }
            #pragma unroll
            for (int mf = 0; mf < 4; mf++) {
                uint32_t ah[4], al[4];
                ldsm4(ah, aAh + mf * 16 * (A_STRIDE * 2) + ks * 32);
                ldsm4(al, aAl + mf * 16 * (A_STRIDE * 2) + ks * 32);
                #pragma unroll
                for (int nf = 0; nf < 4; nf++) {
                    hmma(acc[mf][nf], ah, bh[nf]);
                    hmma(acc[mf][nf], ah, bl[nf]);
                    hmma(acc[mf][nf], al, bh[nf]);
                }
            }
        }
        if (ch < 7) __syncthreads();
    }

    // ---- epilogue ----
    const int g = lane >> 2;
    const int tig = lane & 3;
    #pragma unroll
    for (int nf = 0; nf < 4; nf++) {
        const int nt = n0 + n_warp + nf * 8 + tig * 2;
        const int bt = nt / HWSZ;
        const int pp = nt - bt * HWSZ;
        #pragma unroll
        for (int mf = 0; mf < 4; mf++) {
            const int d0 = dBase + m_warp + mf * 16 + g;
            const float bb0 = sbias[d0 - dBase];
            const float bb1 = sbias[d0 - dBase + 8];
            float2 v0, v1;
            v0.x = acc[mf][nf][0] + bb0;
            v0.y = acc[mf][nf][1] + bb0;
            v1.x = acc[mf][nf][2] + bb1;
            v1.y = acc[mf][nf][3] + bb1;
            stcs2(out + ((size_t)bt * CC + d0) * HWSZ + pp, v0);
            stcs2(out + ((size_t)bt * CC + d0 + 8) * HWSZ + pp, v1);
        }
    }
}

// ---------------------------------------------------------------------------
// launch
// ---------------------------------------------------------------------------
extern "C" void kernel_launch(void* const* d_in, const int* in_sizes, int n_in,
                              void* d_out, int out_size) {
    (void)in_sizes; (void)n_in; (void)out_size;
    const float* s      = (const float*)d_in[0];
    const float* r      = (const float*)d_in[1];
    const float* pw1    = (const float*)d_in[2];
    const float* pb1    = (const float*)d_in[3];
    const float* pw2    = (const float*)d_in[4];
    const float* pb2    = (const float*)d_in[5];
    const float* weight = (const float*)d_in[6];
    const float* bscale = (const float*)d_in[7];
    const float* pww    = (const float*)d_in[8];
    const float* pwb    = (const float*)d_in[9];
    float* out = (float*)d_out;

    pool_kernel<<<BB * CC, 256>>>(r);
    wgen_kernel<<<BB, 256>>>(pw1, pb1, pw2, pb2, weight, bscale);
    wconv_kernel<<<CC * CC / 256, 256>>>(pww);
    dw_kernel<<<BB * CC / 2, 256>>>(s);
    dim3 grid(NTOT / 128, CC / 128, 1);
    pw_mma_kernel<<<grid, 256>>>(pwb, out);
}

// round 10
// speedup vs baseline: 1.8277x; 1.0513x over previous
#include <cuda_runtime.h>
#include <cuda_bf16.h>
#include <cstdint>
#include <cstddef>

// Problem constants
#define BB   32
#define CC   256
#define HH   56
#define WW   56
#define HWSZ 3136          // 56*56
#define GG   4
#define KS   7
#define KK2  49            // 7*7
#define CRR  64            // C / 4
#define NTOT (BB * HWSZ)   // 100352 = 784 * 128

typedef unsigned long long ull;

// Scratch (device globals: allocation-free per harness rules)
__device__ __nv_bfloat16 g_sc_hi[(size_t)BB * CC * HWSZ];  // gelu(dw) bf16 hi
__device__ __nv_bfloat16 g_sc_lo[(size_t)BB * CC * HWSZ];  // gelu(dw) bf16 lo
__device__ float g_pooled[BB * CC];
__device__ float g_wk[(size_t)BB * CC * KK2];              // per-(b,c) 7x7 kernels
__device__ __nv_bfloat16 g_wb_hi[CC * CC];                 // pw_w bf16 hi
__device__ __nv_bfloat16 g_wb_lo[CC * CC];                 // pw_w bf16 lo

// ---------------------------------------------------------------------------
// generic helpers
// ---------------------------------------------------------------------------
__device__ __forceinline__ float gelu_f(float x) {
    return 0.5f * x * (1.0f + erff(x * 0.70710678118654752440f));
}
__device__ __forceinline__ ull pack2(float lo, float hi) {
    ull r; asm("mov.b64 %0, {%1, %2};" : "=l"(r) : "f"(lo), "f"(hi)); return r;
}
__device__ __forceinline__ void fma2(ull& d, ull a, ull b) {
    asm("fma.rn.f32x2 %0, %1, %2, %0;" : "+l"(d) : "l"(a), "l"(b));
}
__device__ __forceinline__ float2 unpack2(ull v) {
    float2 r; asm("mov.b64 {%0, %1}, %2;" : "=f"(r.x), "=f"(r.y) : "l"(v)); return r;
}
__device__ __forceinline__ float4 ldcs4(const float* p) {
    float4 v;
    asm("ld.global.cs.v4.f32 {%0,%1,%2,%3}, [%4];"
        : "=f"(v.x), "=f"(v.y), "=f"(v.z), "=f"(v.w) : "l"(p));
    return v;
}
__device__ __forceinline__ void stcs2(float* p, float2 v) {
    asm("st.global.cs.v2.f32 [%0], {%1,%2};" :: "l"(p), "f"(v.x), "f"(v.y));
}
__device__ __forceinline__ uint32_t pk_bf(__nv_bfloat16 a, __nv_bfloat16 b) {
    __nv_bfloat162 v(a, b);
    return *reinterpret_cast<uint32_t*>(&v);
}
__device__ __forceinline__ uint32_t smem_u32(const void* p) {
    uint32_t a;
    asm("{ .reg .u64 t; cvta.to.shared.u64 t, %1; cvt.u32.u64 %0, t; }"
        : "=r"(a) : "l"(p));
    return a;
}
__device__ __forceinline__ void cpa16(uint32_t dst, const void* src) {
    asm volatile("cp.async.cg.shared.global [%0], [%1], 16;" :: "r"(dst), "l"(src));
}
#define CPA_COMMIT() asm volatile("cp.async.commit_group;" ::: "memory")
#define CPA_WAIT0()  asm volatile("cp.async.wait_group 0;" ::: "memory")
#define CPA_WAIT1()  asm volatile("cp.async.wait_group 1;" ::: "memory")

// HMMA m16n8k16 bf16 (row.col), fp32 accumulate — portable sm_80+ path
__device__ __forceinline__ void hmma(float* c, const uint32_t* a, const uint32_t* b) {
    asm volatile(
        "mma.sync.aligned.m16n8k16.row.col.f32.bf16.bf16.f32 "
        "{%0,%1,%2,%3}, {%4,%5,%6,%7}, {%8,%9}, {%0,%1,%2,%3};"
        : "+f"(c[0]), "+f"(c[1]), "+f"(c[2]), "+f"(c[3])
        : "r"(a[0]), "r"(a[1]), "r"(a[2]), "r"(a[3]), "r"(b[0]), "r"(b[1]));
}
__device__ __forceinline__ void ldsm4(uint32_t* r, uint32_t addr) {
    asm volatile("ldmatrix.sync.aligned.m8n8.x4.shared.b16 {%0,%1,%2,%3}, [%4];"
                 : "=r"(r[0]), "=r"(r[1]), "=r"(r[2]), "=r"(r[3]) : "r"(addr));
}
__device__ __forceinline__ void ldsm4t(uint32_t* r, uint32_t addr) {
    asm volatile("ldmatrix.sync.aligned.m8n8.x4.trans.shared.b16 {%0,%1,%2,%3}, [%4];"
                 : "=r"(r[0]), "=r"(r[1]), "=r"(r[2]), "=r"(r[3]) : "r"(addr));
}

// ---------------------------------------------------------------------------
// Kernel 1: pooled[b,c] = mean over H,W of r
// ---------------------------------------------------------------------------
__global__ void pool_kernel(const float* __restrict__ r) {
    const int bc = blockIdx.x;
    const float* p = r + (size_t)bc * HWSZ;
    float s = 0.f;
    #pragma unroll 4
    for (int i = threadIdx.x; i < HWSZ / 4; i += 256) {
        float4 v = ldcs4(p + i * 4);
        s += (v.x + v.y) + (v.z + v.w);
    }
    __shared__ float red[8];
    #pragma unroll
    for (int o = 16; o > 0; o >>= 1) s += __shfl_down_sync(0xFFFFFFFFu, s, o);
    if ((threadIdx.x & 31) == 0) red[threadIdx.x >> 5] = s;
    __syncthreads();
    if (threadIdx.x < 8) {
        s = red[threadIdx.x];
        #pragma unroll
        for (int o = 4; o > 0; o >>= 1) s += __shfl_down_sync(0xFFu, s, o);
        if (threadIdx.x == 0) g_pooled[bc] = s * (1.0f / (float)HWSZ);
    }
}

// ---------------------------------------------------------------------------
// Kernel 2: SE weight generation -> g_wk[b,c,49]
// ---------------------------------------------------------------------------
__global__ void wgen_kernel(const float* __restrict__ w1, const float* __restrict__ b1,
                            const float* __restrict__ w2, const float* __restrict__ b2,
                            const float* __restrict__ weight, const float* __restrict__ bscale) {
    const int b = blockIdx.x;
    const int t = threadIdx.x;
    __shared__ float ps[CC];
    __shared__ float hs[CRR];

    ps[t] = g_pooled[b * CC + t];
    __syncthreads();

    if (t < CRR) {
        float acc = b1[t];
        const float* wr = w1 + (size_t)t * CC;
        #pragma unroll 4
        for (int c = 0; c < CC; c++) acc = fmaf(ps[c], wr[c], acc);
        hs[t] = gelu_f(acc);
    }
    __syncthreads();

    float vals[GG][2];
    #pragma unroll
    for (int g = 0; g < GG; g++) {
        #pragma unroll
        for (int e = 0; e < 2; e++) {
            const int row = (g * CC + t) * 2 + e;
            float acc = b2[row];
            const float* wr = w2 + (size_t)row * CRR;
            #pragma unroll 4
            for (int k = 0; k < CRR; k++) acc = fmaf(hs[k], wr[k], acc);
            vals[g][e] = acc;
        }
    }

    float m = fmaxf(fmaxf(vals[0][0], vals[1][0]), fmaxf(vals[2][0], vals[3][0]));
    float alpha[GG];
    float ssum = 0.f;
    #pragma unroll
    for (int g = 0; g < GG; g++) { alpha[g] = expf(vals[g][0] - m); ssum += alpha[g]; }
    const float inv = 1.0f / ssum;
    float betasum = 0.f;
    #pragma unroll
    for (int g = 0; g < GG; g++) {
        alpha[g] *= inv;
        betasum += tanhf(vals[g][1] * expf(bscale[g * CC + t]) * 0.1f);
    }

    float* out = g_wk + ((size_t)b * CC + t) * KK2;
    #pragma unroll
    for (int k = 0; k < KK2; k++) {
        float acc = betasum;
        #pragma unroll
        for (int g = 0; g < GG; g++)
            acc = fmaf(alpha[g], weight[((size_t)g * CC + t) * KK2 + k], acc);
        out[k] = acc;
    }
}

// ---------------------------------------------------------------------------
// Kernel 2b: preconvert pw_w -> bf16 hi/lo  (65536 elements)
// ---------------------------------------------------------------------------
__global__ void wconv_kernel(const float* __restrict__ w) {
    const int i = blockIdx.x * 256 + threadIdx.x;
    const float x = w[i];
    const __nv_bfloat16 h = __float2bfloat16(x);
    g_wb_hi[i] = h;
    g_wb_lo[i] = __float2bfloat16(x - __bfloat162float(h));
}

// ---------------------------------------------------------------------------
// Kernel 3: dynamic depthwise 7x7 conv (pad 3) + exact GELU -> bf16 hi/lo
// ---------------------------------------------------------------------------
__global__ void __launch_bounds__(256, 2) dw_kernel(const float* __restrict__ s) {
    const int bc0 = blockIdx.x * 2;
    __shared__ __align__(16) float sm[2][62 * 64];
    __shared__ ull wsm[2][KK2];
    const int t = threadIdx.x;

    {
        float4* z = reinterpret_cast<float4*>(&sm[0][0]);
        const float4 zv = make_float4(0.f, 0.f, 0.f, 0.f);
        #pragma unroll
        for (int i = t; i < 2 * 62 * 64 / 4; i += 256) z[i] = zv;
    }
    if (t < 2 * KK2) {
        const int pl = t / KK2;
        const int k = t - pl * KK2;
        const float w = g_wk[(size_t)(bc0 + pl) * KK2 + k];
        wsm[pl][k] = pack2(w, w);
    }
    __syncthreads();

    for (int i = t; i < 2 * 784; i += 256) {
        const int pl = (i >= 784) ? 1 : 0;
        const int j = i - pl * 784;
        const int y = j / 14;
        const int x4 = j - y * 14;
        const float4 v = ldcs4(s + (size_t)(bc0 + pl) * HWSZ + y * WW + x4 * 4);
        float* dst = &sm[pl][(y + 3) * 64 + 3 + x4 * 4];
        dst[0] = v.x; dst[1] = v.y; dst[2] = v.z; dst[3] = v.w;
    }
    __syncthreads();

    if (t >= 196) return;
    const int pl = t / 98;
    const int v = t - pl * 98;
    const int ytile = v / 7;
    const int xtile = v - ytile * 7;
    const int y0 = ytile * 4;
    const int x0 = xtile * 8;
    const float* __restrict__ smp = sm[pl];
    const ull* __restrict__ wp = wsm[pl];
    const size_t obase = (size_t)(bc0 + pl) * HWSZ;

    ull acc[4][4];
    #pragma unroll
    for (int oy = 0; oy < 4; oy++)
        #pragma unroll
        for (int j = 0; j < 4; j++) acc[oy][j] = 0ull;

    #pragma unroll
    for (int r = 0; r < 10; r++) {
        const float* row = &smp[(y0 + r) * 64 + x0];
        const float4 q0 = *reinterpret_cast<const float4*>(row);
        const float4 q1 = *reinterpret_cast<const float4*>(row + 4);
        const float4 q2 = *reinterpret_cast<const float4*>(row + 8);
        const float4 q3 = *reinterpret_cast<const float4*>(row + 12);
        const float f[16] = {q0.x, q0.y, q0.z, q0.w, q1.x, q1.y, q1.z, q1.w,
                             q2.x, q2.y, q2.z, q2.w, q3.x, q3.y, q3.z, q3.w};
        ull p[13];
        #pragma unroll
        for (int i = 0; i < 13; i++) p[i] = pack2(f[i], f[i + 1]);

        #pragma unroll
        for (int oy = 0; oy < 4; oy++) {
            const int ky = r - oy;
            if (ky >= 0 && ky < 7) {
                #pragma unroll
                for (int kx = 0; kx < 7; kx++) {
                    const ull w = wp[ky * 7 + kx];
                    fma2(acc[oy][0], w, p[kx]);
                    fma2(acc[oy][1], w, p[kx + 2]);
                    fma2(acc[oy][2], w, p[kx + 4]);
                    fma2(acc[oy][3], w, p[kx + 6]);
                }
            }
        }
    }

    #pragma unroll
    for (int oy = 0; oy < 4; oy++) {
        const float2 v0 = unpack2(acc[oy][0]);
        const float2 v1 = unpack2(acc[oy][1]);
        const float2 v2 = unpack2(acc[oy][2]);
        const float2 v3 = unpack2(acc[oy][3]);
        float g[8];
        g[0] = gelu_f(v0.x); g[1] = gelu_f(v0.y); g[2] = gelu_f(v1.x); g[3] = gelu_f(v1.y);
        g[4] = gelu_f(v2.x); g[5] = gelu_f(v2.y); g[6] = gelu_f(v3.x); g[7] = gelu_f(v3.y);
        uint32_t hw[4], lw[4];
        #pragma unroll
        for (int q = 0; q < 4; q++) {
            const __nv_bfloat16 h0 = __float2bfloat16(g[2 * q]);
            const __nv_bfloat16 h1 = __float2bfloat16(g[2 * q + 1]);
            hw[q] = pk_bf(h0, h1);
            lw[q] = pk_bf(__float2bfloat16(g[2 * q] - __bfloat162float(h0)),
                          __float2bfloat16(g[2 * q + 1] - __bfloat162float(h1)));
        }
        const size_t off = obase + (y0 + oy) * WW + x0;
        *reinterpret_cast<uint4*>(g_sc_hi + off) = make_uint4(hw[0], hw[1], hw[2], hw[3]);
        *reinterpret_cast<uint4*>(g_sc_lo + off) = make_uint4(lw[0], lw[1], lw[2], lw[3]);
    }
}

// ---------------------------------------------------------------------------
// Kernel 4: pointwise conv on tensor cores (mma.sync bf16, 3-term split)
// 2-stage cp.async pipeline, K-chunk 16 (16 chunks). Tile 128(d) x 128(n),
// warp tile 64x32, 2 blocks/SM. A smem stride 24 bf16 (48B, conflict-free
// LDSM); B smem stride 136 bf16.
// ---------------------------------------------------------------------------
#define A_STRIDE 24     // bf16 elems per A smem row (48 B)
#define B_STRIDE 136    // bf16 elems per B smem row (272 B)

__global__ void __launch_bounds__(256, 2) pw_mma_kernel(const float* __restrict__ bias,
                                                        float* __restrict__ out) {
    __shared__ __align__(16) __nv_bfloat16 Ah[2][128 * A_STRIDE];
    __shared__ __align__(16) __nv_bfloat16 Al[2][128 * A_STRIDE];
    __shared__ __align__(16) __nv_bfloat16 Bh[2][16 * B_STRIDE];
    __shared__ __align__(16) __nv_bfloat16 Bl[2][16 * B_STRIDE];
    __shared__ float sbias[128];

    const int t = threadIdx.x;
    const int lane = t & 31;
    const int wid = t >> 5;
    const int n0 = blockIdx.x * 128;
    const int dBase = blockIdx.y * 128;

    const int m_warp = (wid >> 2) * 64;   // 0 or 64
    const int n_warp = (wid & 3) * 32;    // 0..96

    if (t < 128) sbias[t] = bias[dBase + t];

    // ---- cp.async assignments (per chunk: 4 x 16B per thread) ----
    const int a_row = t >> 1;
    const int a_half = t & 1;
    const size_t a_g = (size_t)(dBase + a_row) * CC + a_half * 8;
    const uint32_t a_s = (uint32_t)(a_row * A_STRIDE + a_half * 8) * 2;
    const int b_row = t >> 4;
    const int b_seg = t & 15;
    const int n_t = n0 + b_seg * 8;       // 8 | 3136 -> single batch per seg
    const int b_bt = n_t / HWSZ;
    const size_t b_g = ((size_t)b_bt * CC + b_row) * HWSZ + (n_t - b_bt * HWSZ);
    const uint32_t b_s = (uint32_t)(b_row * B_STRIDE + b_seg * 8) * 2;

    const uint32_t sAh[2] = {smem_u32(Ah[0]) + a_s, smem_u32(Ah[1]) + a_s};
    const uint32_t sAl[2] = {smem_u32(Al[0]) + a_s, smem_u32(Al[1]) + a_s};
    const uint32_t sBh[2] = {smem_u32(Bh[0]) + b_s, smem_u32(Bh[1]) + b_s};
    const uint32_t sBl[2] = {smem_u32(Bl[0]) + b_s, smem_u32(Bl[1]) + b_s};

    // ---- LDSM lane addressing ----
    const int a_lrow = m_warp + (lane & 7) + ((lane >> 3) & 1) * 8;
    const uint32_t aA_off = a_lrow * (A_STRIDE * 2) + (lane >> 4) * 16;
    const uint32_t aAh[2] = {smem_u32(Ah[0]) + aA_off, smem_u32(Ah[1]) + aA_off};
    const uint32_t aAl[2] = {smem_u32(Al[0]) + aA_off, smem_u32(Al[1]) + aA_off};
    const int b_krow = ((lane >> 3) & 1) * 8 + (lane & 7);
    const int b_ncol = n_warp + (lane >> 4) * 8;
    const uint32_t aB_off = b_krow * (B_STRIDE * 2) + b_ncol * 2;
    const uint32_t aBh[2] = {smem_u32(Bh[0]) + aB_off, smem_u32(Bh[1]) + aB_off};
    const uint32_t aBl[2] = {smem_u32(Bl[0]) + aB_off, smem_u32(Bl[1]) + aB_off};

    float acc[4][4][4];
    #pragma unroll
    for (int i = 0; i < 4; i++)
        #pragma unroll
        for (int j = 0; j < 4; j++)
            #pragma unroll
            for (int q = 0; q < 4; q++) acc[i][j][q] = 0.f;

    auto load_chunk = [&](int ch, int buf) {
        const int c0 = ch * 16;
        cpa16(sAh[buf], g_wb_hi + a_g + c0);
        cpa16(sAl[buf], g_wb_lo + a_g + c0);
        const size_t bg = b_g + (size_t)c0 * HWSZ;
        cpa16(sBh[buf], g_sc_hi + bg);
        cpa16(sBl[buf], g_sc_lo + bg);
        CPA_COMMIT();
    };

    load_chunk(0, 0);
    for (int ch = 0; ch < 16; ch++) {
        const int buf = ch & 1;
        if (ch < 15) {
            load_chunk(ch + 1, buf ^ 1);
            CPA_WAIT1();
        } else {
            CPA_WAIT0();
        }
        __syncthreads();

        uint32_t bh[4][2], bl[4][2];
        #pragma unroll
        for (int nfp = 0; nfp < 2; nfp++) {
            uint32_t r[4];
            ldsm4t(r, aBh[buf] + nfp * 32);
            bh[nfp * 2 + 0][0] = r[0]; bh[nfp * 2 + 0][1] = r[1];
            bh[nfp * 2 + 1][0] = r[2]; bh[nfp * 2 + 1][1] = r[3];
            ldsm4t(r, aBl[buf] + nfp * 32);
            bl[nfp * 2 + 0][0] = r[0]; bl[nfp * 2 + 0][1] = r[1];
            bl[nfp * 2 + 1][0] = r[2]; bl[nfp * 2 + 1][1] = r[3];
        }
        #pragma unroll
        for (int mf = 0; mf < 4; mf++) {
            uint32_t ah[4], al[4];
            ldsm4(ah, aAh[buf] + mf * 16 * (A_STRIDE * 2));
            ldsm4(al, aAl[buf] + mf * 16 * (A_STRIDE * 2));
            #pragma unroll
            for (int nf = 0; nf < 4; nf++) {
                hmma(acc[mf][nf], ah, bh[nf]);
                hmma(acc[mf][nf], ah, bl[nf]);
                hmma(acc[mf][nf], al, bh[nf]);
            }
        }
        if (ch < 15) __syncthreads();
    }

    // ---- epilogue ----
    const int g = lane >> 2;
    const int tig = lane & 3;
    #pragma unroll
    for (int nf = 0; nf < 4; nf++) {
        const int nt = n0 + n_warp + nf * 8 + tig * 2;
        const int bt = nt / HWSZ;
        const int pp = nt - bt * HWSZ;
        #pragma unroll
        for (int mf = 0; mf < 4; mf++) {
            const int d0 = dBase + m_warp + mf * 16 + g;
            const float bb0 = sbias[d0 - dBase];
            const float bb1 = sbias[d0 - dBase + 8];
            float2 v0, v1;
            v0.x = acc[mf][nf][0] + bb0;
            v0.y = acc[mf][nf][1] + bb0;
            v1.x = acc[mf][nf][2] + bb1;
            v1.y = acc[mf][nf][3] + bb1;
            stcs2(out + ((size_t)bt * CC + d0) * HWSZ + pp, v0);
            stcs2(out + ((size_t)bt * CC + d0 + 8) * HWSZ + pp, v1);
        }
    }
}

// ---------------------------------------------------------------------------
// launch
// ---------------------------------------------------------------------------
extern "C" void kernel_launch(void* const* d_in, const int* in_sizes, int n_in,
                              void* d_out, int out_size) {
    (void)in_sizes; (void)n_in; (void)out_size;
    const float* s      = (const float*)d_in[0];
    const float* r      = (const float*)d_in[1];
    const float* pw1    = (const float*)d_in[2];
    const float* pb1    = (const float*)d_in[3];
    const float* pw2    = (const float*)d_in[4];
    const float* pb2    = (const float*)d_in[5];
    const float* weight = (const float*)d_in[6];
    const float* bscale = (const float*)d_in[7];
    const float* pww    = (const float*)d_in[8];
    const float* pwb    = (const float*)d_in[9];
    float* out = (float*)d_out;

    pool_kernel<<<BB * CC, 256>>>(r);
    wgen_kernel<<<BB, 256>>>(pw1, pb1, pw2, pb2, weight, bscale);
    wconv_kernel<<<CC * CC / 256, 256>>>(pww);
    dw_kernel<<<BB * CC / 2, 256>>>(s);
    dim3 grid(NTOT / 128, CC / 128, 1);
    pw_mma_kernel<<<grid, 256>>>(pwb, out);
}

// round 11
// speedup vs baseline: 1.8585x; 1.0169x over previous
#include <cuda_runtime.h>
#include <cuda_bf16.h>
#include <cstdint>
#include <cstddef>

// Problem constants
#define BB   32
#define CC   256
#define HH   56
#define WW   56
#define HWSZ 3136          // 56*56
#define GG   4
#define KS   7
#define KK2  49            // 7*7
#define CRR  64            // C / 4
#define NTOT (BB * HWSZ)   // 100352 = 784 * 128

typedef unsigned long long ull;

// Scratch (device globals: allocation-free per harness rules)
__device__ __nv_bfloat16 g_sc_hi[(size_t)BB * CC * HWSZ];  // gelu(dw) bf16 hi
__device__ __nv_bfloat16 g_sc_lo[(size_t)BB * CC * HWSZ];  // gelu(dw) bf16 lo
__device__ float g_pooled[BB * CC];
__device__ float g_wk[(size_t)BB * CC * KK2];              // per-(b,c) 7x7 kernels
__device__ __nv_bfloat16 g_wb_hi[CC * CC];                 // pw_w bf16 hi
__device__ __nv_bfloat16 g_wb_lo[CC * CC];                 // pw_w bf16 lo

// ---------------------------------------------------------------------------
// generic helpers
// ---------------------------------------------------------------------------
__device__ __forceinline__ float gelu_f(float x) {
    return 0.5f * x * (1.0f + erff(x * 0.70710678118654752440f));
}
__device__ __forceinline__ ull pack2(float lo, float hi) {
    ull r; asm("mov.b64 %0, {%1, %2};" : "=l"(r) : "f"(lo), "f"(hi)); return r;
}
__device__ __forceinline__ void fma2(ull& d, ull a, ull b) {
    asm("fma.rn.f32x2 %0, %1, %2, %0;" : "+l"(d) : "l"(a), "l"(b));
}
__device__ __forceinline__ float2 unpack2(ull v) {
    float2 r; asm("mov.b64 {%0, %1}, %2;" : "=f"(r.x), "=f"(r.y) : "l"(v)); return r;
}
__device__ __forceinline__ float4 ldcs4(const float* p) {
    float4 v;
    asm("ld.global.cs.v4.f32 {%0,%1,%2,%3}, [%4];"
        : "=f"(v.x), "=f"(v.y), "=f"(v.z), "=f"(v.w) : "l"(p));
    return v;
}
__device__ __forceinline__ void stcs2(float* p, float2 v) {
    asm("st.global.cs.v2.f32 [%0], {%1,%2};" :: "l"(p), "f"(v.x), "f"(v.y));
}
__device__ __forceinline__ uint32_t pk_bf(__nv_bfloat16 a, __nv_bfloat16 b) {
    __nv_bfloat162 v(a, b);
    return *reinterpret_cast<uint32_t*>(&v);
}
__device__ __forceinline__ uint32_t smem_u32(const void* p) {
    uint32_t a;
    asm("{ .reg .u64 t; cvta.to.shared.u64 t, %1; cvt.u32.u64 %0, t; }"
        : "=r"(a) : "l"(p));
    return a;
}
__device__ __forceinline__ void cpa16(uint32_t dst, const void* src) {
    asm volatile("cp.async.cg.shared.global [%0], [%1], 16;" :: "r"(dst), "l"(src));
}
#define CPA_COMMIT() asm volatile("cp.async.commit_group;" ::: "memory")
#define CPA_WAIT0()  asm volatile("cp.async.wait_group 0;" ::: "memory")
#define CPA_WAIT1()  asm volatile("cp.async.wait_group 1;" ::: "memory")

// HMMA m16n8k16 bf16 (row.col), fp32 accumulate — portable sm_80+ path
__device__ __forceinline__ void hmma(float* c, const uint32_t* a, const uint32_t* b) {
    asm volatile(
        "mma.sync.aligned.m16n8k16.row.col.f32.bf16.bf16.f32 "
        "{%0,%1,%2,%3}, {%4,%5,%6,%7}, {%8,%9}, {%0,%1,%2,%3};"
        : "+f"(c[0]), "+f"(c[1]), "+f"(c[2]), "+f"(c[3])
        : "r"(a[0]), "r"(a[1]), "r"(a[2]), "r"(a[3]), "r"(b[0]), "r"(b[1]));
}
__device__ __forceinline__ void ldsm4(uint32_t* r, uint32_t addr) {
    asm volatile("ldmatrix.sync.aligned.m8n8.x4.shared.b16 {%0,%1,%2,%3}, [%4];"
                 : "=r"(r[0]), "=r"(r[1]), "=r"(r[2]), "=r"(r[3]) : "r"(addr));
}
__device__ __forceinline__ void ldsm4t(uint32_t* r, uint32_t addr) {
    asm volatile("ldmatrix.sync.aligned.m8n8.x4.trans.shared.b16 {%0,%1,%2,%3}, [%4];"
                 : "=r"(r[0]), "=r"(r[1]), "=r"(r[2]), "=r"(r[3]) : "r"(addr));
}

// ---------------------------------------------------------------------------
// Kernel 1: pooled[b,c] = mean over H,W of r
// ---------------------------------------------------------------------------
__global__ void pool_kernel(const float* __restrict__ r) {
    const int bc = blockIdx.x;
    const float* p = r + (size_t)bc * HWSZ;
    float s = 0.f;
    #pragma unroll 4
    for (int i = threadIdx.x; i < HWSZ / 4; i += 256) {
        float4 v = ldcs4(p + i * 4);
        s += (v.x + v.y) + (v.z + v.w);
    }
    __shared__ float red[8];
    #pragma unroll
    for (int o = 16; o > 0; o >>= 1) s += __shfl_down_sync(0xFFFFFFFFu, s, o);
    if ((threadIdx.x & 31) == 0) red[threadIdx.x >> 5] = s;
    __syncthreads();
    if (threadIdx.x < 8) {
        s = red[threadIdx.x];
        #pragma unroll
        for (int o = 4; o > 0; o >>= 1) s += __shfl_down_sync(0xFFu, s, o);
        if (threadIdx.x == 0) g_pooled[bc] = s * (1.0f / (float)HWSZ);
    }
}

// ---------------------------------------------------------------------------
// Kernel 2: SE weight generation -> g_wk[b,c,49]
// ---------------------------------------------------------------------------
__global__ void wgen_kernel(const float* __restrict__ w1, const float* __restrict__ b1,
                            const float* __restrict__ w2, const float* __restrict__ b2,
                            const float* __restrict__ weight, const float* __restrict__ bscale) {
    const int b = blockIdx.x;
    const int t = threadIdx.x;
    __shared__ float ps[CC];
    __shared__ float hs[CRR];

    ps[t] = g_pooled[b * CC + t];
    __syncthreads();

    if (t < CRR) {
        float acc = b1[t];
        const float* wr = w1 + (size_t)t * CC;
        #pragma unroll 4
        for (int c = 0; c < CC; c++) acc = fmaf(ps[c], wr[c], acc);
        hs[t] = gelu_f(acc);
    }
    __syncthreads();

    float vals[GG][2];
    #pragma unroll
    for (int g = 0; g < GG; g++) {
        #pragma unroll
        for (int e = 0; e < 2; e++) {
            const int row = (g * CC + t) * 2 + e;
            float acc = b2[row];
            const float* wr = w2 + (size_t)row * CRR;
            #pragma unroll 4
            for (int k = 0; k < CRR; k++) acc = fmaf(hs[k], wr[k], acc);
            vals[g][e] = acc;
        }
    }

    float m = fmaxf(fmaxf(vals[0][0], vals[1][0]), fmaxf(vals[2][0], vals[3][0]));
    float alpha[GG];
    float ssum = 0.f;
    #pragma unroll
    for (int g = 0; g < GG; g++) { alpha[g] = expf(vals[g][0] - m); ssum += alpha[g]; }
    const float inv = 1.0f / ssum;
    float betasum = 0.f;
    #pragma unroll
    for (int g = 0; g < GG; g++) {
        alpha[g] *= inv;
        betasum += tanhf(vals[g][1] * expf(bscale[g * CC + t]) * 0.1f);
    }

    float* out = g_wk + ((size_t)b * CC + t) * KK2;
    #pragma unroll
    for (int k = 0; k < KK2; k++) {
        float acc = betasum;
        #pragma unroll
        for (int g = 0; g < GG; g++)
            acc = fmaf(alpha[g], weight[((size_t)g * CC + t) * KK2 + k], acc);
        out[k] = acc;
    }
}

// ---------------------------------------------------------------------------
// Kernel 2b: preconvert pw_w -> bf16 hi/lo  (65536 elements)
// ---------------------------------------------------------------------------
__global__ void wconv_kernel(const float* __restrict__ w) {
    const int i = blockIdx.x * 256 + threadIdx.x;
    const float x = w[i];
    const __nv_bfloat16 h = __float2bfloat16(x);
    g_wb_hi[i] = h;
    g_wb_lo[i] = __float2bfloat16(x - __bfloat162float(h));
}

// ---------------------------------------------------------------------------
// Kernel 3: dynamic depthwise 7x7 conv (pad 3) + exact GELU -> bf16 hi/lo
// (byte-identical to R10 — frozen control)
// ---------------------------------------------------------------------------
__global__ void __launch_bounds__(256, 2) dw_kernel(const float* __restrict__ s) {
    const int bc0 = blockIdx.x * 2;
    __shared__ __align__(16) float sm[2][62 * 64];
    __shared__ ull wsm[2][KK2];
    const int t = threadIdx.x;

    {
        float4* z = reinterpret_cast<float4*>(&sm[0][0]);
        const float4 zv = make_float4(0.f, 0.f, 0.f, 0.f);
        #pragma unroll
        for (int i = t; i < 2 * 62 * 64 / 4; i += 256) z[i] = zv;
    }
    if (t < 2 * KK2) {
        const int pl = t / KK2;
        const int k = t - pl * KK2;
        const float w = g_wk[(size_t)(bc0 + pl) * KK2 + k];
        wsm[pl][k] = pack2(w, w);
    }
    __syncthreads();

    for (int i = t; i < 2 * 784; i += 256) {
        const int pl = (i >= 784) ? 1 : 0;
        const int j = i - pl * 784;
        const int y = j / 14;
        const int x4 = j - y * 14;
        const float4 v = ldcs4(s + (size_t)(bc0 + pl) * HWSZ + y * WW + x4 * 4);
        float* dst = &sm[pl][(y + 3) * 64 + 3 + x4 * 4];
        dst[0] = v.x; dst[1] = v.y; dst[2] = v.z; dst[3] = v.w;
    }
    __syncthreads();

    if (t >= 196) return;
    const int pl = t / 98;
    const int v = t - pl * 98;
    const int ytile = v / 7;
    const int xtile = v - ytile * 7;
    const int y0 = ytile * 4;
    const int x0 = xtile * 8;
    const float* __restrict__ smp = sm[pl];
    const ull* __restrict__ wp = wsm[pl];
    const size_t obase = (size_t)(bc0 + pl) * HWSZ;

    ull acc[4][4];
    #pragma unroll
    for (int oy = 0; oy < 4; oy++)
        #pragma unroll
        for (int j = 0; j < 4; j++) acc[oy][j] = 0ull;

    #pragma unroll
    for (int r = 0; r < 10; r++) {
        const float* row = &smp[(y0 + r) * 64 + x0];
        const float4 q0 = *reinterpret_cast<const float4*>(row);
        const float4 q1 = *reinterpret_cast<const float4*>(row + 4);
        const float4 q2 = *reinterpret_cast<const float4*>(row + 8);
        const float4 q3 = *reinterpret_cast<const float4*>(row + 12);
        const float f[16] = {q0.x, q0.y, q0.z, q0.w, q1.x, q1.y, q1.z, q1.w,
                             q2.x, q2.y, q2.z, q2.w, q3.x, q3.y, q3.z, q3.w};
        ull p[13];
        #pragma unroll
        for (int i = 0; i < 13; i++) p[i] = pack2(f[i], f[i + 1]);

        #pragma unroll
        for (int oy = 0; oy < 4; oy++) {
            const int ky = r - oy;
            if (ky >= 0 && ky < 7) {
                #pragma unroll
                for (int kx = 0; kx < 7; kx++) {
                    const ull w = wp[ky * 7 + kx];
                    fma2(acc[oy][0], w, p[kx]);
                    fma2(acc[oy][1], w, p[kx + 2]);
                    fma2(acc[oy][2], w, p[kx + 4]);
                    fma2(acc[oy][3], w, p[kx + 6]);
                }
            }
        }
    }

    #pragma unroll
    for (int oy = 0; oy < 4; oy++) {
        const float2 v0 = unpack2(acc[oy][0]);
        const float2 v1 = unpack2(acc[oy][1]);
        const float2 v2 = unpack2(acc[oy][2]);
        const float2 v3 = unpack2(acc[oy][3]);
        float g[8];
        g[0] = gelu_f(v0.x); g[1] = gelu_f(v0.y); g[2] = gelu_f(v1.x); g[3] = gelu_f(v1.y);
        g[4] = gelu_f(v2.x); g[5] = gelu_f(v2.y); g[6] = gelu_f(v3.x); g[7] = gelu_f(v3.y);
        uint32_t hw[4], lw[4];
        #pragma unroll
        for (int q = 0; q < 4; q++) {
            const __nv_bfloat16 h0 = __float2bfloat16(g[2 * q]);
            const __nv_bfloat16 h1 = __float2bfloat16(g[2 * q + 1]);
            hw[q] = pk_bf(h0, h1);
            lw[q] = pk_bf(__float2bfloat16(g[2 * q] - __bfloat162float(h0)),
                          __float2bfloat16(g[2 * q + 1] - __bfloat162float(h1)));
        }
        const size_t off = obase + (y0 + oy) * WW + x0;
        *reinterpret_cast<uint4*>(g_sc_hi + off) = make_uint4(hw[0], hw[1], hw[2], hw[3]);
        *reinterpret_cast<uint4*>(g_sc_lo + off) = make_uint4(lw[0], lw[1], lw[2], lw[3]);
    }
}

// ---------------------------------------------------------------------------
// Kernel 4: pointwise conv on tensor cores (mma.sync bf16, 3-term split)
// 3-stage cp.async ring, ONE __syncthreads per chunk, K-chunk 16 (16 chunks).
// Tile 128(d) x 128(n), warp tile 64x32, 2 blocks/SM.
// Unpadded smem + XOR swizzles (exactly 48 KB static):
//   A: row 32B, 16B-half swapped by ((row>>2)&1)  -> conflict-free LDSM
//   B: row 256B, 16B-chunk ^= (krow&7)            -> conflict-free LDSM.trans
// ---------------------------------------------------------------------------
#define A_MAT_BYTES 4096                  // 128 rows x 32 B
#define B_MAT_BYTES 4096                  // 16 rows x 256 B
#define STAGE_BYTES (2 * A_MAT_BYTES)     // hi+lo per stage per operand

__global__ void __launch_bounds__(256, 2) pw_mma_kernel(const float* __restrict__ bias,
                                                        float* __restrict__ out) {
    // [stage][hi/lo][data] ; A then B. Total = 3*2*4096*2 = 49152 B (exactly 48KB)
    __shared__ __align__(16) __nv_bfloat16 sA[3][2][A_MAT_BYTES / 2];
    __shared__ __align__(16) __nv_bfloat16 sB[3][2][B_MAT_BYTES / 2];

    const int t = threadIdx.x;
    const int lane = t & 31;
    const int wid = t >> 5;
    const int n0 = blockIdx.x * 128;
    const int dBase = blockIdx.y * 128;

    const int m_warp = (wid >> 2) * 64;   // 0 or 64
    const int n_warp = (wid & 3) * 32;    // 0..96

    const uint32_t baseA = smem_u32(sA);
    const uint32_t baseB = smem_u32(sB);

    // ---- cp.async destinations (swizzled) ----
    const int a_row = t >> 1;             // 0..127
    const int a_half = t & 1;             // 0/1
    const size_t a_g = (size_t)(dBase + a_row) * CC + a_half * 8;
    const uint32_t a_off = (uint32_t)(a_row * 32 + ((a_half ^ ((a_row >> 2) & 1)) << 4));

    const int b_row = t >> 4;             // 0..15 (k)
    const int b_seg = t & 15;             // 16B chunk (8 n)
    const int n_t = n0 + b_seg * 8;       // 8 | 3136 -> single batch per seg
    const int b_bt = n_t / HWSZ;
    const size_t b_g = ((size_t)b_bt * CC + b_row) * HWSZ + (n_t - b_bt * HWSZ);
    const uint32_t b_off = (uint32_t)(b_row * 256 + ((b_seg ^ (b_row & 7)) << 4));

    // ---- LDSM source addresses (swizzled offsets, stage-invariant) ----
    uint32_t aA_off[4];
    #pragma unroll
    for (int mf = 0; mf < 4; mf++) {
        const int row = m_warp + mf * 16 + (lane & 7) + ((lane >> 3) & 1) * 8;
        const int half = lane >> 4;
        aA_off[mf] = (uint32_t)(row * 32 + ((half ^ ((row >> 2) & 1)) << 4));
    }
    const int b_krow = ((lane >> 3) & 1) * 8 + (lane & 7);
    uint32_t aB_off[2];
    #pragma unroll
    for (int nfp = 0; nfp < 2; nfp++) {
        const int chunk = (n_warp >> 3) + (lane >> 4) + nfp * 2;
        aB_off[nfp] = (uint32_t)(b_krow * 256 + ((chunk ^ (b_krow & 7)) << 4));
    }

    float acc[4][4][4];
    #pragma unroll
    for (int i = 0; i < 4; i++)
        #pragma unroll
        for (int j = 0; j < 4; j++)
            #pragma unroll
            for (int q = 0; q < 4; q++) acc[i][j][q] = 0.f;

    auto load_chunk = [&](int ch, int buf) {
        const int c0 = ch * 16;
        const uint32_t sa = baseA + (uint32_t)buf * STAGE_BYTES;
        const uint32_t sb = baseB + (uint32_t)buf * STAGE_BYTES;
        cpa16(sa + a_off, g_wb_hi + a_g + c0);
        cpa16(sa + A_MAT_BYTES + a_off, g_wb_lo + a_g + c0);
        const size_t bg = b_g + (size_t)c0 * HWSZ;
        cpa16(sb + b_off, g_sc_hi + bg);
        cpa16(sb + B_MAT_BYTES + b_off, g_sc_lo + bg);
        CPA_COMMIT();
    };

    load_chunk(0, 0);
    load_chunk(1, 1);

    int buf = 0;
    for (int ch = 0; ch < 16; ch++) {
        CPA_WAIT1();
        __syncthreads();

        const uint32_t sa = baseA + (uint32_t)buf * STAGE_BYTES;
        const uint32_t sb = baseB + (uint32_t)buf * STAGE_BYTES;

        uint32_t bh[4][2], bl[4][2];
        #pragma unroll
        for (int nfp = 0; nfp < 2; nfp++) {
            uint32_t r[4];
            ldsm4t(r, sb + aB_off[nfp]);
            bh[nfp * 2 + 0][0] = r[0]; bh[nfp * 2 + 0][1] = r[1];
            bh[nfp * 2 + 1][0] = r[2]; bh[nfp * 2 + 1][1] = r[3];
            ldsm4t(r, sb + B_MAT_BYTES + aB_off[nfp]);
            bl[nfp * 2 + 0][0] = r[0]; bl[nfp * 2 + 0][1] = r[1];
            bl[nfp * 2 + 1][0] = r[2]; bl[nfp * 2 + 1][1] = r[3];
        }
        #pragma unroll
        for (int mf = 0; mf < 4; mf++) {
            uint32_t ah[4], al[4];
            ldsm4(ah, sa + aA_off[mf]);
            ldsm4(al, sa + A_MAT_BYTES + aA_off[mf]);
            #pragma unroll
            for (int nf = 0; nf < 4; nf++) {
                hmma(acc[mf][nf], ah, bh[nf]);
                hmma(acc[mf][nf], ah, bl[nf]);
                hmma(acc[mf][nf], al, bh[nf]);
            }
        }

        const int nxt = ch + 2;
        if (nxt < 16) {
            int nbuf = buf - 1;
            if (nbuf < 0) nbuf = 2;      // (ch+2)%3 given buf=(ch)%3
            load_chunk(nxt, nbuf);
        } else {
            CPA_COMMIT();                 // keep group counting consistent
        }
        buf++;
        if (buf == 3) buf = 0;
    }

    // ---- epilogue (bias via __ldg; no smem) ----
    const int g = lane >> 2;
    const int tig = lane & 3;
    #pragma unroll
    for (int mf = 0; mf < 4; mf++) {
        const int d0 = dBase + m_warp + mf * 16 + g;
        const float bb0 = __ldg(bias + d0);
        const float bb1 = __ldg(bias + d0 + 8);
        #pragma unroll
        for (int nf = 0; nf < 4; nf++) {
            const int nt = n0 + n_warp + nf * 8 + tig * 2;
            const int bt = nt / HWSZ;
            const int pp = nt - bt * HWSZ;
            float2 v0, v1;
            v0.x = acc[mf][nf][0] + bb0;
            v0.y = acc[mf][nf][1] + bb0;
            v1.x = acc[mf][nf][2] + bb1;
            v1.y = acc[mf][nf][3] + bb1;
            stcs2(out + ((size_t)bt * CC + d0) * HWSZ + pp, v0);
            stcs2(out + ((size_t)bt * CC + d0 + 8) * HWSZ + pp, v1);
        }
    }
}

// ---------------------------------------------------------------------------
// launch
// ---------------------------------------------------------------------------
extern "C" void kernel_launch(void* const* d_in, const int* in_sizes, int n_in,
                              void* d_out, int out_size) {
    (void)in_sizes; (void)n_in; (void)out_size;
    const float* s      = (const float*)d_in[0];
    const float* r      = (const float*)d_in[1];
    const float* pw1    = (const float*)d_in[2];
    const float* pb1    = (const float*)d_in[3];
    const float* pw2    = (const float*)d_in[4];
    const float* pb2    = (const float*)d_in[5];
    const float* weight = (const float*)d_in[6];
    const float* bscale = (const float*)d_in[7];
    const float* pww    = (const float*)d_in[8];
    const float* pwb    = (const float*)d_in[9];
    float* out = (float*)d_out;

    pool_kernel<<<BB * CC, 256>>>(r);
    wgen_kernel<<<BB, 256>>>(pw1, pb1, pw2, pb2, weight, bscale);
    wconv_kernel<<<CC * CC / 256, 256>>>(pww);
    dw_kernel<<<BB * CC / 2, 256>>>(s);
    dim3 grid(NTOT / 128, CC / 128, 1);
    pw_mma_kernel<<<grid, 256>>>(pwb, out);
}

// round 12
// speedup vs baseline: 1.8588x; 1.0002x over previous
#include <cuda_runtime.h>
#include <cuda_bf16.h>
#include <cstdint>
#include <cstddef>

// Problem constants
#define BB   32
#define CC   256
#define HH   56
#define WW   56
#define HWSZ 3136          // 56*56
#define GG   4
#define KS   7
#define KK2  49            // 7*7
#define CRR  64            // C / 4
#define NTOT (BB * HWSZ)   // 100352 = 784 * 128

typedef unsigned long long ull;

// Scratch (device globals: allocation-free per harness rules)
__device__ __nv_bfloat16 g_sc_hi[(size_t)BB * CC * HWSZ];  // gelu(dw) bf16 hi
__device__ __nv_bfloat16 g_sc_lo[(size_t)BB * CC * HWSZ];  // gelu(dw) bf16 lo
__device__ float g_pooled[BB * CC];
__device__ float g_wk[(size_t)BB * CC * KK2];              // per-(b,c) 7x7 kernels
__device__ __nv_bfloat16 g_wb_hi[CC * CC];                 // pw_w bf16 hi
__device__ __nv_bfloat16 g_wb_lo[CC * CC];                 // pw_w bf16 lo

// ---------------------------------------------------------------------------
// generic helpers
// ---------------------------------------------------------------------------
__device__ __forceinline__ float gelu_f(float x) {
    return 0.5f * x * (1.0f + erff(x * 0.70710678118654752440f));
}
__device__ __forceinline__ ull pack2(float lo, float hi) {
    ull r; asm("mov.b64 %0, {%1, %2};" : "=l"(r) : "f"(lo), "f"(hi)); return r;
}
__device__ __forceinline__ void fma2(ull& d, ull a, ull b) {
    asm("fma.rn.f32x2 %0, %1, %2, %0;" : "+l"(d) : "l"(a), "l"(b));
}
__device__ __forceinline__ float2 unpack2(ull v) {
    float2 r; asm("mov.b64 {%0, %1}, %2;" : "=f"(r.x), "=f"(r.y) : "l"(v)); return r;
}
__device__ __forceinline__ float4 ldcs4(const float* p) {
    float4 v;
    asm("ld.global.cs.v4.f32 {%0,%1,%2,%3}, [%4];"
        : "=f"(v.x), "=f"(v.y), "=f"(v.z), "=f"(v.w) : "l"(p));
    return v;
}
__device__ __forceinline__ void stcs2(float* p, float2 v) {
    asm("st.global.cs.v2.f32 [%0], {%1,%2};" :: "l"(p), "f"(v.x), "f"(v.y));
}
__device__ __forceinline__ uint32_t pk_bf(__nv_bfloat16 a, __nv_bfloat16 b) {
    __nv_bfloat162 v(a, b);
    return *reinterpret_cast<uint32_t*>(&v);
}
__device__ __forceinline__ uint32_t smem_u32(const void* p) {
    uint32_t a;
    asm("{ .reg .u64 t; cvta.to.shared.u64 t, %1; cvt.u32.u64 %0, t; }"
        : "=r"(a) : "l"(p));
    return a;
}
__device__ __forceinline__ void cpa16(uint32_t dst, const void* src) {
    asm volatile("cp.async.cg.shared.global [%0], [%1], 16;" :: "r"(dst), "l"(src));
}
#define CPA_COMMIT() asm volatile("cp.async.commit_group;" ::: "memory")
#define CPA_WAIT0()  asm volatile("cp.async.wait_group 0;" ::: "memory")
#define CPA_WAIT1()  asm volatile("cp.async.wait_group 1;" ::: "memory")

// HMMA m16n8k16 bf16 (row.col), fp32 accumulate — portable sm_80+ path
__device__ __forceinline__ void hmma(float* c, const uint32_t* a, const uint32_t* b) {
    asm volatile(
        "mma.sync.aligned.m16n8k16.row.col.f32.bf16.bf16.f32 "
        "{%0,%1,%2,%3}, {%4,%5,%6,%7}, {%8,%9}, {%0,%1,%2,%3};"
        : "+f"(c[0]), "+f"(c[1]), "+f"(c[2]), "+f"(c[3])
        : "r"(a[0]), "r"(a[1]), "r"(a[2]), "r"(a[3]), "r"(b[0]), "r"(b[1]));
}
__device__ __forceinline__ void ldsm4(uint32_t* r, uint32_t addr) {
    asm volatile("ldmatrix.sync.aligned.m8n8.x4.shared.b16 {%0,%1,%2,%3}, [%4];"
                 : "=r"(r[0]), "=r"(r[1]), "=r"(r[2]), "=r"(r[3]) : "r"(addr));
}
__device__ __forceinline__ void ldsm4t(uint32_t* r, uint32_t addr) {
    asm volatile("ldmatrix.sync.aligned.m8n8.x4.trans.shared.b16 {%0,%1,%2,%3}, [%4];"
                 : "=r"(r[0]), "=r"(r[1]), "=r"(r[2]), "=r"(r[3]) : "r"(addr));
}

// ---------------------------------------------------------------------------
// Kernel 1: pooled[b,c] = mean over H,W of r
// ---------------------------------------------------------------------------
__global__ void pool_kernel(const float* __restrict__ r) {
    const int bc = blockIdx.x;
    const float* p = r + (size_t)bc * HWSZ;
    float s = 0.f;
    #pragma unroll 4
    for (int i = threadIdx.x; i < HWSZ / 4; i += 256) {
        float4 v = ldcs4(p + i * 4);
        s += (v.x + v.y) + (v.z + v.w);
    }
    __shared__ float red[8];
    #pragma unroll
    for (int o = 16; o > 0; o >>= 1) s += __shfl_down_sync(0xFFFFFFFFu, s, o);
    if ((threadIdx.x & 31) == 0) red[threadIdx.x >> 5] = s;
    __syncthreads();
    if (threadIdx.x < 8) {
        s = red[threadIdx.x];
        #pragma unroll
        for (int o = 4; o > 0; o >>= 1) s += __shfl_down_sync(0xFFu, s, o);
        if (threadIdx.x == 0) g_pooled[bc] = s * (1.0f / (float)HWSZ);
    }
}

// ---------------------------------------------------------------------------
// Kernel 2: SE weight generation -> g_wk[b,c,49]
// ---------------------------------------------------------------------------
__global__ void wgen_kernel(const float* __restrict__ w1, const float* __restrict__ b1,
                            const float* __restrict__ w2, const float* __restrict__ b2,
                            const float* __restrict__ weight, const float* __restrict__ bscale) {
    const int b = blockIdx.x;
    const int t = threadIdx.x;
    __shared__ float ps[CC];
    __shared__ float hs[CRR];

    ps[t] = g_pooled[b * CC + t];
    __syncthreads();

    if (t < CRR) {
        float acc = b1[t];
        const float* wr = w1 + (size_t)t * CC;
        #pragma unroll 4
        for (int c = 0; c < CC; c++) acc = fmaf(ps[c], wr[c], acc);
        hs[t] = gelu_f(acc);
    }
    __syncthreads();

    float vals[GG][2];
    #pragma unroll
    for (int g = 0; g < GG; g++) {
        #pragma unroll
        for (int e = 0; e < 2; e++) {
            const int row = (g * CC + t) * 2 + e;
            float acc = b2[row];
            const float* wr = w2 + (size_t)row * CRR;
            #pragma unroll 4
            for (int k = 0; k < CRR; k++) acc = fmaf(hs[k], wr[k], acc);
            vals[g][e] = acc;
        }
    }

    float m = fmaxf(fmaxf(vals[0][0], vals[1][0]), fmaxf(vals[2][0], vals[3][0]));
    float alpha[GG];
    float ssum = 0.f;
    #pragma unroll
    for (int g = 0; g < GG; g++) { alpha[g] = expf(vals[g][0] - m); ssum += alpha[g]; }
    const float inv = 1.0f / ssum;
    float betasum = 0.f;
    #pragma unroll
    for (int g = 0; g < GG; g++) {
        alpha[g] *= inv;
        betasum += tanhf(vals[g][1] * expf(bscale[g * CC + t]) * 0.1f);
    }

    float* out = g_wk + ((size_t)b * CC + t) * KK2;
    #pragma unroll
    for (int k = 0; k < KK2; k++) {
        float acc = betasum;
        #pragma unroll
        for (int g = 0; g < GG; g++)
            acc = fmaf(alpha[g], weight[((size_t)g * CC + t) * KK2 + k], acc);
        out[k] = acc;
    }
}

// ---------------------------------------------------------------------------
// Kernel 2b: preconvert pw_w -> bf16 hi/lo  (65536 elements)
// ---------------------------------------------------------------------------
__global__ void wconv_kernel(const float* __restrict__ w) {
    const int i = blockIdx.x * 256 + threadIdx.x;
    const float x = w[i];
    const __nv_bfloat16 h = __float2bfloat16(x);
    g_wb_hi[i] = h;
    g_wb_lo[i] = __float2bfloat16(x - __bfloat162float(h));
}

// ---------------------------------------------------------------------------
// Kernel 3: dynamic depthwise 7x7 conv (pad 3) + exact GELU -> bf16 hi/lo
// (byte-identical to R10 — frozen control)
// ---------------------------------------------------------------------------
__global__ void __launch_bounds__(256, 2) dw_kernel(const float* __restrict__ s) {
    const int bc0 = blockIdx.x * 2;
    __shared__ __align__(16) float sm[2][62 * 64];
    __shared__ ull wsm[2][KK2];
    const int t = threadIdx.x;

    {
        float4* z = reinterpret_cast<float4*>(&sm[0][0]);
        const float4 zv = make_float4(0.f, 0.f, 0.f, 0.f);
        #pragma unroll
        for (int i = t; i < 2 * 62 * 64 / 4; i += 256) z[i] = zv;
    }
    if (t < 2 * KK2) {
        const int pl = t / KK2;
        const int k = t - pl * KK2;
        const float w = g_wk[(size_t)(bc0 + pl) * KK2 + k];
        wsm[pl][k] = pack2(w, w);
    }
    __syncthreads();

    for (int i = t; i < 2 * 784; i += 256) {
        const int pl = (i >= 784) ? 1 : 0;
        const int j = i - pl * 784;
        const int y = j / 14;
        const int x4 = j - y * 14;
        const float4 v = ldcs4(s + (size_t)(bc0 + pl) * HWSZ + y * WW + x4 * 4);
        float* dst = &sm[pl][(y + 3) * 64 + 3 + x4 * 4];
        dst[0] = v.x; dst[1] = v.y; dst[2] = v.z; dst[3] = v.w;
    }
    __syncthreads();

    if (t >= 196) return;
    const int pl = t / 98;
    const int v = t - pl * 98;
    const int ytile = v / 7;
    const int xtile = v - ytile * 7;
    const int y0 = ytile * 4;
    const int x0 = xtile * 8;
    const float* __restrict__ smp = sm[pl];
    const ull* __restrict__ wp = wsm[pl];
    const size_t obase = (size_t)(bc0 + pl) * HWSZ;

    ull acc[4][4];
    #pragma unroll
    for (int oy = 0; oy < 4; oy++)
        #pragma unroll
        for (int j = 0; j < 4; j++) acc[oy][j] = 0ull;

    #pragma unroll
    for (int r = 0; r < 10; r++) {
        const float* row = &smp[(y0 + r) * 64 + x0];
        const float4 q0 = *reinterpret_cast<const float4*>(row);
        const float4 q1 = *reinterpret_cast<const float4*>(row + 4);
        const float4 q2 = *reinterpret_cast<const float4*>(row + 8);
        const float4 q3 = *reinterpret_cast<const float4*>(row + 12);
        const float f[16] = {q0.x, q0.y, q0.z, q0.w, q1.x, q1.y, q1.z, q1.w,
                             q2.x, q2.y, q2.z, q2.w, q3.x, q3.y, q3.z, q3.w};
        ull p[13];
        #pragma unroll
        for (int i = 0; i < 13; i++) p[i] = pack2(f[i], f[i + 1]);

        #pragma unroll
        for (int oy = 0; oy < 4; oy++) {
            const int ky = r - oy;
            if (ky >= 0 && ky < 7) {
                #pragma unroll
                for (int kx = 0; kx < 7; kx++) {
                    const ull w = wp[ky * 7 + kx];
                    fma2(acc[oy][0], w, p[kx]);
                    fma2(acc[oy][1], w, p[kx + 2]);
                    fma2(acc[oy][2], w, p[kx + 4]);
                    fma2(acc[oy][3], w, p[kx + 6]);
                }
            }
        }
    }

    #pragma unroll
    for (int oy = 0; oy < 4; oy++) {
        const float2 v0 = unpack2(acc[oy][0]);
        const float2 v1 = unpack2(acc[oy][1]);
        const float2 v2 = unpack2(acc[oy][2]);
        const float2 v3 = unpack2(acc[oy][3]);
        float g[8];
        g[0] = gelu_f(v0.x); g[1] = gelu_f(v0.y); g[2] = gelu_f(v1.x); g[3] = gelu_f(v1.y);
        g[4] = gelu_f(v2.x); g[5] = gelu_f(v2.y); g[6] = gelu_f(v3.x); g[7] = gelu_f(v3.y);
        uint32_t hw[4], lw[4];
        #pragma unroll
        for (int q = 0; q < 4; q++) {
            const __nv_bfloat16 h0 = __float2bfloat16(g[2 * q]);
            const __nv_bfloat16 h1 = __float2bfloat16(g[2 * q + 1]);
            hw[q] = pk_bf(h0, h1);
            lw[q] = pk_bf(__float2bfloat16(g[2 * q] - __bfloat162float(h0)),
                          __float2bfloat16(g[2 * q + 1] - __bfloat162float(h1)));
        }
        const size_t off = obase + (y0 + oy) * WW + x0;
        *reinterpret_cast<uint4*>(g_sc_hi + off) = make_uint4(hw[0], hw[1], hw[2], hw[3]);
        *reinterpret_cast<uint4*>(g_sc_lo + off) = make_uint4(lw[0], lw[1], lw[2], lw[3]);
    }
}

// ---------------------------------------------------------------------------
// Kernel 4: pointwise conv on tensor cores (mma.sync bf16, 3-term split)
// 3-stage cp.async ring, ONE __syncthreads per chunk, K-chunk 16 (16 chunks).
// Tile 128(d) x 128(n), warp tile 64x32, 2 blocks/SM.
// Unpadded smem + XOR swizzles (exactly 48 KB static):
//   A: row 32B, 16B-half swapped by ((row>>2)&1)  -> conflict-free LDSM
//   B: row 256B, 16B-chunk ^= (krow&7)            -> conflict-free LDSM.trans
// ---------------------------------------------------------------------------
#define A_MAT_BYTES 4096                  // 128 rows x 32 B
#define B_MAT_BYTES 4096                  // 16 rows x 256 B
#define STAGE_BYTES (2 * A_MAT_BYTES)     // hi+lo per stage per operand

__global__ void __launch_bounds__(256, 2) pw_mma_kernel(const float* __restrict__ bias,
                                                        float* __restrict__ out) {
    // [stage][hi/lo][data] ; A then B. Total = 3*2*4096*2 = 49152 B (exactly 48KB)
    __shared__ __align__(16) __nv_bfloat16 sA[3][2][A_MAT_BYTES / 2];
    __shared__ __align__(16) __nv_bfloat16 sB[3][2][B_MAT_BYTES / 2];

    const int t = threadIdx.x;
    const int lane = t & 31;
    const int wid = t >> 5;
    const int n0 = blockIdx.x * 128;
    const int dBase = blockIdx.y * 128;

    const int m_warp = (wid >> 2) * 64;   // 0 or 64
    const int n_warp = (wid & 3) * 32;    // 0..96

    const uint32_t baseA = smem_u32(sA);
    const uint32_t baseB = smem_u32(sB);

    // ---- cp.async destinations (swizzled) ----
    const int a_row = t >> 1;             // 0..127
    const int a_half = t & 1;             // 0/1
    const size_t a_g = (size_t)(dBase + a_row) * CC + a_half * 8;
    const uint32_t a_off = (uint32_t)(a_row * 32 + ((a_half ^ ((a_row >> 2) & 1)) << 4));

    const int b_row = t >> 4;             // 0..15 (k)
    const int b_seg = t & 15;             // 16B chunk (8 n)
    const int n_t = n0 + b_seg * 8;       // 8 | 3136 -> single batch per seg
    const int b_bt = n_t / HWSZ;
    const size_t b_g = ((size_t)b_bt * CC + b_row) * HWSZ + (n_t - b_bt * HWSZ);
    const uint32_t b_off = (uint32_t)(b_row * 256 + ((b_seg ^ (b_row & 7)) << 4));

    // ---- LDSM source addresses (swizzled offsets, stage-invariant) ----
    uint32_t aA_off[4];
    #pragma unroll
    for (int mf = 0; mf < 4; mf++) {
        const int row = m_warp + mf * 16 + (lane & 7) + ((lane >> 3) & 1) * 8;
        const int half = lane >> 4;
        aA_off[mf] = (uint32_t)(row * 32 + ((half ^ ((row >> 2) & 1)) << 4));
    }
    const int b_krow = ((lane >> 3) & 1) * 8 + (lane & 7);
    uint32_t aB_off[2];
    #pragma unroll
    for (int nfp = 0; nfp < 2; nfp++) {
        const int chunk = (n_warp >> 3) + (lane >> 4) + nfp * 2;
        aB_off[nfp] = (uint32_t)(b_krow * 256 + ((chunk ^ (b_krow & 7)) << 4));
    }

    float acc[4][4][4];
    #pragma unroll
    for (int i = 0; i < 4; i++)
        #pragma unroll
        for (int j = 0; j < 4; j++)
            #pragma unroll
            for (int q = 0; q < 4; q++) acc[i][j][q] = 0.f;

    auto load_chunk = [&](int ch, int buf) {
        const int c0 = ch * 16;
        const uint32_t sa = baseA + (uint32_t)buf * STAGE_BYTES;
        const uint32_t sb = baseB + (uint32_t)buf * STAGE_BYTES;
        cpa16(sa + a_off, g_wb_hi + a_g + c0);
        cpa16(sa + A_MAT_BYTES + a_off, g_wb_lo + a_g + c0);
        const size_t bg = b_g + (size_t)c0 * HWSZ;
        cpa16(sb + b_off, g_sc_hi + bg);
        cpa16(sb + B_MAT_BYTES + b_off, g_sc_lo + bg);
        CPA_COMMIT();
    };

    load_chunk(0, 0);
    load_chunk(1, 1);

    int buf = 0;
    for (int ch = 0; ch < 16; ch++) {
        CPA_WAIT1();
        __syncthreads();

        const uint32_t sa = baseA + (uint32_t)buf * STAGE_BYTES;
        const uint32_t sb = baseB + (uint32_t)buf * STAGE_BYTES;

        uint32_t bh[4][2], bl[4][2];
        #pragma unroll
        for (int nfp = 0; nfp < 2; nfp++) {
            uint32_t r[4];
            ldsm4t(r, sb + aB_off[nfp]);
            bh[nfp * 2 + 0][0] = r[0]; bh[nfp * 2 + 0][1] = r[1];
            bh[nfp * 2 + 1][0] = r[2]; bh[nfp * 2 + 1][1] = r[3];
            ldsm4t(r, sb + B_MAT_BYTES + aB_off[nfp]);
            bl[nfp * 2 + 0][0] = r[0]; bl[nfp * 2 + 0][1] = r[1];
            bl[nfp * 2 + 1][0] = r[2]; bl[nfp * 2 + 1][1] = r[3];
        }
        #pragma unroll
        for (int mf = 0; mf < 4; mf++) {
            uint32_t ah[4], al[4];
            ldsm4(ah, sa + aA_off[mf]);
            ldsm4(al, sa + A_MAT_BYTES + aA_off[mf]);
            #pragma unroll
            for (int nf = 0; nf < 4; nf++) {
                hmma(acc[mf][nf], ah, bh[nf]);
                hmma(acc[mf][nf], ah, bl[nf]);
                hmma(acc[mf][nf], al, bh[nf]);
            }
        }

        const int nxt = ch + 2;
        if (nxt < 16) {
            int nbuf = buf - 1;
            if (nbuf < 0) nbuf = 2;      // (ch+2)%3 given buf=(ch)%3
            load_chunk(nxt, nbuf);
        } else {
            CPA_COMMIT();                 // keep group counting consistent
        }
        buf++;
        if (buf == 3) buf = 0;
    }

    // ---- epilogue (bias via __ldg; no smem) ----
    const int g = lane >> 2;
    const int tig = lane & 3;
    #pragma unroll
    for (int mf = 0; mf < 4; mf++) {
        const int d0 = dBase + m_warp + mf * 16 + g;
        const float bb0 = __ldg(bias + d0);
        const float bb1 = __ldg(bias + d0 + 8);
        #pragma unroll
        for (int nf = 0; nf < 4; nf++) {
            const int nt = n0 + n_warp + nf * 8 + tig * 2;
            const int bt = nt / HWSZ;
            const int pp = nt - bt * HWSZ;
            float2 v0, v1;
            v0.x = acc[mf][nf][0] + bb0;
            v0.y = acc[mf][nf][1] + bb0;
            v1.x = acc[mf][nf][2] + bb1;
            v1.y = acc[mf][nf][3] + bb1;
            stcs2(out + ((size_t)bt * CC + d0) * HWSZ + pp, v0);
            stcs2(out + ((size_t)bt * CC + d0 + 8) * HWSZ + pp, v1);
        }
    }
}

// ---------------------------------------------------------------------------
// launch
// ---------------------------------------------------------------------------
extern "C" void kernel_launch(void* const* d_in, const int* in_sizes, int n_in,
                              void* d_out, int out_size) {
    (void)in_sizes; (void)n_in; (void)out_size;
    const float* s      = (const float*)d_in[0];
    const float* r      = (const float*)d_in[1];
    const float* pw1    = (const float*)d_in[2];
    const float* pb1    = (const float*)d_in[3];
    const float* pw2    = (const float*)d_in[4];
    const float* pb2    = (const float*)d_in[5];
    const float* weight = (const float*)d_in[6];
    const float* bscale = (const float*)d_in[7];
    const float* pww    = (const float*)d_in[8];
    const float* pwb    = (const float*)d_in[9];
    float* out = (float*)d_out;

    pool_kernel<<<BB * CC, 256>>>(r);
    wgen_kernel<<<BB, 256>>>(pw1, pb1, pw2, pb2, weight, bscale);
    wconv_kernel<<<CC * CC / 256, 256>>>(pww);
    dw_kernel<<<BB * CC / 2, 256>>>(s);
    dim3 grid(NTOT / 128, CC / 128, 1);
    pw_mma_kernel<<<grid, 256>>>(pwb, out);
}